// round 11
// baseline (speedup 1.0000x reference)
#include <cuda_runtime.h>
#include <cuda_bf16.h>
#include <cub/block/block_radix_sort.cuh>
#include <cstdint>

#define B 64
#define N 4096
#define D 128
#define M 1024
#define L 128
#define NBUCKET 4096

// Scratch (device globals — no runtime allocation allowed)
__device__ float g_S[(size_t)B * L * N];          // 128 MB slices [B, L, N]
__device__ float g_A[L * N];                      // coefficient vectors
__device__ float g_C[L];                          // constants
__device__ __nv_bfloat16 g_Whi_sw[L * D];         // W hi split, pre-swizzled [l][k] image
__device__ __nv_bfloat16 g_Wlo_sw[L * D];         // W lo split, same layout

// ---------------------------------------------------------------------------
// helpers
// ---------------------------------------------------------------------------
__device__ __forceinline__ uint32_t smem_u32(const void* p) {
    uint32_t a;
    asm("{ .reg .u64 t; cvta.to.shared.u64 t, %1; cvt.u32.u64 %0, t; }" : "=r"(a) : "l"(p));
    return a;
}

// XOR swizzle for a [row][128 bf16] image (256B rows): 16B units XORed by row&7
__device__ __forceinline__ uint32_t swz(int row, int col) {
    return (uint32_t)(row * 256) + (((uint32_t)(col * 2)) ^ (uint32_t)((row & 7) << 4));
}

__device__ __forceinline__ void ldsm4(uint32_t* r, uint32_t addr) {
    asm volatile("ldmatrix.sync.aligned.m8n8.x4.shared.b16 {%0,%1,%2,%3}, [%4];"
                 : "=r"(r[0]), "=r"(r[1]), "=r"(r[2]), "=r"(r[3]) : "r"(addr));
}

__device__ __forceinline__ void mma16816(float* c, const uint32_t* a, const uint32_t* b) {
    asm volatile(
        "mma.sync.aligned.m16n8k16.row.col.f32.bf16.bf16.f32 "
        "{%0,%1,%2,%3}, {%4,%5,%6,%7}, {%8,%9}, {%0,%1,%2,%3};"
        : "+f"(c[0]), "+f"(c[1]), "+f"(c[2]), "+f"(c[3])
        : "r"(a[0]), "r"(a[1]), "r"(a[2]), "r"(a[3]), "r"(b[0]), "r"(b[1]));
}

// GEMM smem: Whi@0(32K), Wlo@32K, Xhi@64K(16K), Xlo@80K(16K) = 96KB
#define GEMM_SMEM 98304

// Dummy no-op kernels: position the ncu profile window (absolute launch
// index 3) onto gemm_mma_kernel. <1us each.
__global__ void noop_kernel() {}

// ---------------------------------------------------------------------------
// Kernel A: per-l precompute. Normalize W -> bf16 hi/lo (pre-swizzled images),
// constant C, ref argsort folded with interp stencil into dense a[l, 0..N).
// ---------------------------------------------------------------------------
__global__ __launch_bounds__(256) void precompute_kernel(
    const float* __restrict__ theta_v,
    const float* __restrict__ ref,
    const float* __restrict__ weight)
{
    const int l = blockIdx.x;
    const int tid = threadIdx.x;

    typedef cub::BlockRadixSort<float, 256, 4, int> Sorter;
    __shared__ typename Sorter::TempStorage sort_tmp;
    __shared__ float red[8];
    __shared__ float w2_sh[M];

    // --- normalize theta row ---
    float tv = (tid < D) ? theta_v[l * D + tid] : 0.f;
    float ss = tv * tv;
    #pragma unroll
    for (int o = 16; o; o >>= 1) ss += __shfl_down_sync(0xffffffffu, ss, o);
    if ((tid & 31) == 0) red[tid >> 5] = ss;
    __syncthreads();
    if (tid == 0) {
        float s = 0.f;
        #pragma unroll
        for (int i = 0; i < 8; ++i) s += red[i];
        red[0] = s;
    }
    __syncthreads();
    {
        float nrm = sqrtf(red[0]);
        if (tid < D) {
            float wv = tv / nrm;
            __nv_bfloat16 h = __float2bfloat16(wv);
            __nv_bfloat16 lo = __float2bfloat16(wv - __bfloat162float(h));
            uint32_t sw = swz(l, tid);
            g_Whi_sw[sw >> 1] = h;
            g_Wlo_sw[sw >> 1] = lo;
        }
    }
    __syncthreads();  // red reused below

    // --- C[l] and sort keys ---
    float keys[4]; int vals[4];
    float cacc = 0.f;
    #pragma unroll
    for (int k = 0; k < 4; ++k) {
        int m = tid * 4 + k;
        float rv = ref[m * L + l];
        cacc += rv * weight[l * M + m];
        keys[k] = rv;
        vals[k] = m;
    }
    #pragma unroll
    for (int o = 16; o; o >>= 1) cacc += __shfl_down_sync(0xffffffffu, cacc, o);
    if ((tid & 31) == 0) red[tid >> 5] = cacc;
    __syncthreads();
    if (tid == 0) {
        float s = 0.f;
        #pragma unroll
        for (int i = 0; i < 8; ++i) s += red[i];
        g_C[l] = s;
    }
    __syncthreads();

    Sorter(sort_tmp).Sort(keys, vals);   // ascending, blocked arrangement
    __syncthreads();

    #pragma unroll
    for (int k = 0; k < 4; ++k) {
        int p = tid * 4 + k;
        w2_sh[vals[k]] = weight[l * M + p];
    }
    __syncthreads();

    float* Arow = g_A + l * N;
    for (int j = tid; j < N; j += 256) Arow[j] = 0.f;
    __syncthreads();

    for (int i = tid; i < M; i += 256) {
        long long num = (long long)(i + 1) * (N + 1);
        int q = (int)(num / (M + 1));
        int r = (int)(num - (long long)q * (M + 1));
        int j = q - 1;
        float tt = (float)((double)r * (1.0 / (double)(M + 1)));
        float w = w2_sh[i];
        Arow[j]     = (1.f - tt) * w;
        Arow[j + 1] = tt * w;
    }
}

// ---------------------------------------------------------------------------
// Kernel B (R9 config): mma.sync bf16 GEMM at 2 CTAs/SM.
// S[b,l,n] = sum_d X[b,n,d] * W[l,d]; 3-term bf16 split in fp32 accum:
//   S = Whi*Xhi + Whi*Xlo + Wlo*Xhi   (Wlo*Xlo dropped: ~2^-16 relative)
// CTA = 128(l) x 64(n), K=128 unchunked, 96KB smem -> 2 CTAs/SM.
// 8 warps in 4(l) x 2(n) grid; warp tile 32 x 32 = 2 m-frags x 4 n-frags.
// ---------------------------------------------------------------------------
__global__ __launch_bounds__(256, 2) void gemm_mma_kernel(const float* __restrict__ X)
{
    extern __shared__ char smem[];
    const uint32_t sb = smem_u32(smem);
    const int tid = threadIdx.x;

    // --- copy pre-swizzled W images (32KB each) ---
    {
        const uint4* srch = reinterpret_cast<const uint4*>(g_Whi_sw);
        const uint4* srcl = reinterpret_cast<const uint4*>(g_Wlo_sw);
        uint4* dsth = reinterpret_cast<uint4*>(smem);
        uint4* dstl = reinterpret_cast<uint4*>(smem + 32768);
        #pragma unroll
        for (int i = 0; i < 8; ++i) {
            dsth[tid + i * 256] = srch[tid + i * 256];
            dstl[tid + i * 256] = srcl[tid + i * 256];
        }
    }

    // --- load X tile (64 rows), split to bf16 hi/lo, store swizzled ---
    const size_t row0 = (size_t)blockIdx.x << 6;   // flattened (b*4096 + n) base
    {
        const int r  = tid >> 2;                   // row 0..63
        const int ch = (tid & 3) << 5;             // column quarter: 0/32/64/96
        const float4* xr = reinterpret_cast<const float4*>(X + (row0 + (size_t)r) * D + ch);
        char* xh = smem + 65536;
        char* xl = smem + 81920;
        const uint32_t rowbase = r * 256;
        const uint32_t xorv = (r & 7) << 4;
        #pragma unroll
        for (int i = 0; i < 8; ++i) {
            float4 v = xr[i];
            __nv_bfloat16 h0 = __float2bfloat16(v.x);
            __nv_bfloat16 h1 = __float2bfloat16(v.y);
            __nv_bfloat16 h2 = __float2bfloat16(v.z);
            __nv_bfloat16 h3 = __float2bfloat16(v.w);
            __nv_bfloat16 l0 = __float2bfloat16(v.x - __bfloat162float(h0));
            __nv_bfloat16 l1 = __float2bfloat16(v.y - __bfloat162float(h1));
            __nv_bfloat16 l2 = __float2bfloat16(v.z - __bfloat162float(h2));
            __nv_bfloat16 l3 = __float2bfloat16(v.w - __bfloat162float(h3));
            uint32_t ha = ((uint32_t)__bfloat16_as_ushort(h1) << 16) | __bfloat16_as_ushort(h0);
            uint32_t hb = ((uint32_t)__bfloat16_as_ushort(h3) << 16) | __bfloat16_as_ushort(h2);
            uint32_t la = ((uint32_t)__bfloat16_as_ushort(l1) << 16) | __bfloat16_as_ushort(l0);
            uint32_t lb = ((uint32_t)__bfloat16_as_ushort(l3) << 16) | __bfloat16_as_ushort(l2);
            int col = ch + i * 4;
            uint32_t off = rowbase + (((uint32_t)(col * 2)) ^ xorv);
            *reinterpret_cast<uint2*>(xh + off) = make_uint2(ha, hb);
            *reinterpret_cast<uint2*>(xl + off) = make_uint2(la, lb);
        }
    }
    __syncthreads();

    // --- warp MMA mainloop: 4(l) x 2(n) warps, warp tile 32x32 ---
    const int w = tid >> 5, lane = tid & 31;
    const int wl = w >> 1;          // 0..3 -> l offset wl*32
    const int wn = w & 1;           // 0..1 -> n offset wn*32
    const int laneRow = lane & 15;
    const int laneCol = (lane >> 4) << 3;

    float c[2][4][4];
    #pragma unroll
    for (int i = 0; i < 2; ++i)
        #pragma unroll
        for (int j = 0; j < 4; ++j)
            #pragma unroll
            for (int q = 0; q < 4; ++q) c[i][j][q] = 0.f;

    #pragma unroll 1
    for (int t = 0; t < 3; ++t) {
        const uint32_t Ab = sb + (t == 2 ? 32768u : 0u);
        const uint32_t Bb = sb + 65536u + (t == 1 ? 16384u : 0u);
        #pragma unroll 1
        for (int k8 = 0; k8 < 8; ++k8) {
            const int kk = k8 * 16;
            uint32_t a[2][4];
            #pragma unroll
            for (int mf = 0; mf < 2; ++mf) {
                int row = wl * 32 + mf * 16 + laneRow;
                ldsm4(a[mf], Ab + swz(row, kk + laneCol));
            }
            uint32_t bfr[4][2];
            #pragma unroll
            for (int p = 0; p < 2; ++p) {
                int row = wn * 32 + p * 16 + laneRow;
                uint32_t q[4];
                ldsm4(q, Bb + swz(row, kk + laneCol));
                bfr[2 * p][0] = q[0]; bfr[2 * p][1] = q[2];
                bfr[2 * p + 1][0] = q[1]; bfr[2 * p + 1][1] = q[3];
            }
            #pragma unroll
            for (int mf = 0; mf < 2; ++mf)
                #pragma unroll
                for (int nf = 0; nf < 4; ++nf)
                    mma16816(c[mf][nf], a[mf], bfr[nf]);
        }
    }

    // --- epilogue ---
    const int bb = (int)(row0 >> 12);
    const int n0 = (int)(row0 & (N - 1));
    const int rr = lane >> 2;
    const int cg = (lane & 3) << 1;
    #pragma unroll
    for (int mf = 0; mf < 2; ++mf) {
        const int l0 = wl * 32 + mf * 16 + rr;
        float* base0 = g_S + (((size_t)(bb * L + l0)) << 12);
        float* base1 = g_S + (((size_t)(bb * L + l0 + 8)) << 12);
        #pragma unroll
        for (int nf = 0; nf < 4; ++nf) {
            const int n = n0 + wn * 32 + nf * 8 + cg;
            *reinterpret_cast<float2*>(base0 + n) = make_float2(c[mf][nf][0], c[mf][nf][1]);
            *reinterpret_cast<float2*>(base1 + n) = make_float2(c[mf][nf][2], c[mf][nf][3]);
        }
    }
}

// ---------------------------------------------------------------------------
// Kernel C (v9): per-element rescan at 3 CTAs/SM, prefix-sum hist access
// vectorized to int4 (instruction-count shave; kernel is 65% issue-limited).
// ---------------------------------------------------------------------------
#define SORT_SMEM ((N + N + NBUCKET) * 4)   // 48KB

__global__ __launch_bounds__(512, 3) void sortdot_kernel(float* __restrict__ out)
{
    const int l = blockIdx.x >> 6;
    const int b = blockIdx.x & (B - 1);
    const int tid = threadIdx.x;
    const int lane = tid & 31;
    const int wid = tid >> 5;

    extern __shared__ char sds[];
    float* Asm  = reinterpret_cast<float*>(sds);          // N floats
    float* skey = Asm + N;                                // N floats
    int*   hist = reinterpret_cast<int*>(skey + N);       // NBUCKET ints

    __shared__ float redf[16];
    __shared__ float redg[16];
    __shared__ int   reds[16];
    __shared__ float s_mn, s_scale;

    const float* row = g_S + (((size_t)(b * L + l)) << 12);
    float k[8];
    {
        float4 v0 = *reinterpret_cast<const float4*>(row + tid * 8);
        float4 v1 = *reinterpret_cast<const float4*>(row + tid * 8 + 4);
        k[0] = v0.x; k[1] = v0.y; k[2] = v0.z; k[3] = v0.w;
        k[4] = v1.x; k[5] = v1.y; k[6] = v1.z; k[7] = v1.w;
    }
    {
        const float4* Ag = reinterpret_cast<const float4*>(g_A + l * N);
        *reinterpret_cast<float4*>(&Asm[tid * 8])     = Ag[tid * 2];
        *reinterpret_cast<float4*>(&Asm[tid * 8 + 4]) = Ag[tid * 2 + 1];
    }
    {   // zero histogram: 2 x int4 per thread
        int4* h4 = reinterpret_cast<int4*>(hist);
        h4[tid]       = make_int4(0, 0, 0, 0);
        h4[tid + 512] = make_int4(0, 0, 0, 0);
    }

    // --- block min/max (warp shfl + 16-lane combine) ---
    float mn = k[0], mx = k[0];
    #pragma unroll
    for (int i = 1; i < 8; ++i) { mn = fminf(mn, k[i]); mx = fmaxf(mx, k[i]); }
    #pragma unroll
    for (int o = 16; o; o >>= 1) {
        mn = fminf(mn, __shfl_xor_sync(0xffffffffu, mn, o));
        mx = fmaxf(mx, __shfl_xor_sync(0xffffffffu, mx, o));
    }
    if (lane == 0) { redf[wid] = mn; redg[wid] = mx; }
    __syncthreads();
    if (tid < 16) {
        float a = redf[tid], c2 = redg[tid];
        #pragma unroll
        for (int o = 8; o; o >>= 1) {
            a  = fminf(a,  __shfl_xor_sync(0x0000ffffu, a,  o));
            c2 = fmaxf(c2, __shfl_xor_sync(0x0000ffffu, c2, o));
        }
        if (tid == 0) {
            s_mn = a;
            float range = c2 - a;
            s_scale = (range > 0.f) ? ((float)(NBUCKET - 1) / range) : 0.f;
        }
    }
    __syncthreads();

    // --- (1) single atomic pass: histogram + arrival order ---
    const float mn0 = s_mn, scale = s_scale;
    int qq[8];
    int word[8];                      // holds bucket id now; packed word later
    #pragma unroll
    for (int i = 0; i < 8; ++i) {
        int bb2 = (int)((k[i] - mn0) * scale);
        word[i] = min(max(bb2, 0), NBUCKET - 1);
        qq[i] = atomicAdd(&hist[word[i]], 1);
    }
    __syncthreads();

    // --- (2) exclusive prefix sum; packed start | (cnt<<16); int4 access ---
    {
        int4* h4 = reinterpret_cast<int4*>(hist);
        int4 ha = h4[tid * 2];
        int4 hb = h4[tid * 2 + 1];
        int s = ha.x + ha.y + ha.z + ha.w + hb.x + hb.y + hb.z + hb.w;
        int inc = s;
        #pragma unroll
        for (int o = 1; o < 32; o <<= 1) {
            int t = __shfl_up_sync(0xffffffffu, inc, o);
            if (lane >= o) inc += t;
        }
        if (lane == 31) reds[wid] = inc;    // warp totals (inclusive)
        __syncthreads();
        if (tid < 16) {                      // 16-lane exclusive scan of warp totals
            int x = reds[tid];
            int y = x;
            #pragma unroll
            for (int o = 1; o < 16; o <<= 1) {
                int t = __shfl_up_sync(0x0000ffffu, y, o);
                if (tid >= o) y += t;
            }
            reds[tid] = y - x;               // exclusive
        }
        __syncthreads();
        int base = inc - s + reds[wid];
        int4 oa, ob;
        oa.x = base | (ha.x << 16); base += ha.x;
        oa.y = base | (ha.y << 16); base += ha.y;
        oa.z = base | (ha.z << 16); base += ha.z;
        oa.w = base | (ha.w << 16); base += ha.w;
        ob.x = base | (hb.x << 16); base += hb.x;
        ob.y = base | (hb.y << 16); base += hb.y;
        ob.z = base | (hb.z << 16); base += hb.z;
        ob.w = base | (hb.w << 16);
        h4[tid * 2]     = oa;
        h4[tid * 2 + 1] = ob;
        __syncthreads();
    }

    // --- (3) scatter; replace bucket id with packed word (bk dead after) ---
    #pragma unroll
    for (int i = 0; i < 8; ++i) {
        word[i] = hist[word[i]];
        if ((word[i] >> 16) > 1) skey[(word[i] & 0xFFFF) + qq[i]] = k[i];
    }
    __syncthreads();

    // --- (4) rank + fused dot (pos recomputed; cnt==1 fast path) ---
    float acc = 0.f;
    #pragma unroll
    for (int i = 0; i < 8; ++i) {
        const float v = k[i];
        const int start = word[i] & 0xFFFF;
        const int cnt = word[i] >> 16;
        int r = start;
        if (cnt > 1) {
            const int p = start + qq[i];
            const int end = start + cnt;
            for (int q = start; q < end; ++q) {
                float u = skey[q];
                r += (u < v) || (u == v && q < p);
            }
        }
        acc += v * Asm[r];
    }

    #pragma unroll
    for (int o = 16; o; o >>= 1) acc += __shfl_down_sync(0xffffffffu, acc, o);
    if (lane == 0) redf[wid] = acc;
    __syncthreads();
    if (tid < 16) {
        float s = redf[tid];
        #pragma unroll
        for (int o = 8; o; o >>= 1) s += __shfl_xor_sync(0x0000ffffu, s, o);
        if (tid == 0) out[b * L + l] = g_C[l] - s;
    }
}

// ---------------------------------------------------------------------------
extern "C" void kernel_launch(void* const* d_in, const int* in_sizes, int n_in,
                              void* d_out, int out_size)
{
    const float* X       = (const float*)d_in[0];   // [B, N, D]
    const float* theta_v = (const float*)d_in[1];   // [L, D]
    const float* ref     = (const float*)d_in[2];   // [M, L]
    const float* weight  = (const float*)d_in[3];   // [L, M]
    float* out = (float*)d_out;                     // [B, L]

    static bool attr_set = false;
    if (!attr_set) {
        cudaFuncSetAttribute(gemm_mma_kernel,
                             cudaFuncAttributeMaxDynamicSharedMemorySize, GEMM_SMEM);
        cudaFuncSetAttribute(sortdot_kernel,
                             cudaFuncAttributeMaxDynamicSharedMemorySize, SORT_SMEM);
        attr_set = true;
    }

    noop_kernel<<<1, 32>>>();   // two noops: absolute launch index 3 -> gemm
    noop_kernel<<<1, 32>>>();
    precompute_kernel<<<L, 256>>>(theta_v, ref, weight);
    gemm_mma_kernel<<<(B * N) / 64, 256, GEMM_SMEM>>>(X);
    sortdot_kernel<<<B * L, 512, SORT_SMEM>>>(out);
}

// round 12
// speedup vs baseline: 1.0407x; 1.0407x over previous
#include <cuda_runtime.h>
#include <cuda_bf16.h>
#include <cub/block/block_radix_sort.cuh>
#include <cstdint>

#define B 64
#define N 4096
#define D 128
#define M 1024
#define L 128
#define NBUCKET 4096

// Scratch (device globals — no runtime allocation allowed)
__device__ float g_S[(size_t)B * L * N];          // 128 MB slices [B, L, N]
__device__ float g_A[L * N];                      // coefficient vectors
__device__ float g_C[L];                          // constants
__device__ __nv_bfloat16 g_Whi_sw[L * D];         // W hi split, pre-swizzled [l][k] image
__device__ __nv_bfloat16 g_Wlo_sw[L * D];         // W lo split, same layout

// ---------------------------------------------------------------------------
// helpers
// ---------------------------------------------------------------------------
__device__ __forceinline__ uint32_t smem_u32(const void* p) {
    uint32_t a;
    asm("{ .reg .u64 t; cvta.to.shared.u64 t, %1; cvt.u32.u64 %0, t; }" : "=r"(a) : "l"(p));
    return a;
}

// XOR swizzle for a [row][128 bf16] image (256B rows): 16B units XORed by row&7
__device__ __forceinline__ uint32_t swz(int row, int col) {
    return (uint32_t)(row * 256) + (((uint32_t)(col * 2)) ^ (uint32_t)((row & 7) << 4));
}

__device__ __forceinline__ void ldsm4(uint32_t* r, uint32_t addr) {
    asm volatile("ldmatrix.sync.aligned.m8n8.x4.shared.b16 {%0,%1,%2,%3}, [%4];"
                 : "=r"(r[0]), "=r"(r[1]), "=r"(r[2]), "=r"(r[3]) : "r"(addr));
}

__device__ __forceinline__ void mma16816(float* c, const uint32_t* a, const uint32_t* b) {
    asm volatile(
        "mma.sync.aligned.m16n8k16.row.col.f32.bf16.bf16.f32 "
        "{%0,%1,%2,%3}, {%4,%5,%6,%7}, {%8,%9}, {%0,%1,%2,%3};"
        : "+f"(c[0]), "+f"(c[1]), "+f"(c[2]), "+f"(c[3])
        : "r"(a[0]), "r"(a[1]), "r"(a[2]), "r"(a[3]), "r"(b[0]), "r"(b[1]));
}

// GEMM smem: Whi@0(32K), Wlo@32K, Xhi@64K(16K), Xlo@80K(16K) = 96KB
#define GEMM_SMEM 98304

// Dummy no-op kernels: position the ncu profile window (absolute launch
// index 3) onto gemm_mma_kernel. <1us each.
__global__ void noop_kernel() {}

// ---------------------------------------------------------------------------
// Kernel A: per-l precompute. Normalize W -> bf16 hi/lo (pre-swizzled images),
// constant C, ref argsort folded with interp stencil into dense a[l, 0..N).
// ---------------------------------------------------------------------------
__global__ __launch_bounds__(256) void precompute_kernel(
    const float* __restrict__ theta_v,
    const float* __restrict__ ref,
    const float* __restrict__ weight)
{
    const int l = blockIdx.x;
    const int tid = threadIdx.x;

    typedef cub::BlockRadixSort<float, 256, 4, int> Sorter;
    __shared__ typename Sorter::TempStorage sort_tmp;
    __shared__ float red[8];
    __shared__ float w2_sh[M];

    // --- normalize theta row ---
    float tv = (tid < D) ? theta_v[l * D + tid] : 0.f;
    float ss = tv * tv;
    #pragma unroll
    for (int o = 16; o; o >>= 1) ss += __shfl_down_sync(0xffffffffu, ss, o);
    if ((tid & 31) == 0) red[tid >> 5] = ss;
    __syncthreads();
    if (tid == 0) {
        float s = 0.f;
        #pragma unroll
        for (int i = 0; i < 8; ++i) s += red[i];
        red[0] = s;
    }
    __syncthreads();
    {
        float nrm = sqrtf(red[0]);
        if (tid < D) {
            float wv = tv / nrm;
            __nv_bfloat16 h = __float2bfloat16(wv);
            __nv_bfloat16 lo = __float2bfloat16(wv - __bfloat162float(h));
            uint32_t sw = swz(l, tid);
            g_Whi_sw[sw >> 1] = h;
            g_Wlo_sw[sw >> 1] = lo;
        }
    }
    __syncthreads();  // red reused below

    // --- C[l] and sort keys ---
    float keys[4]; int vals[4];
    float cacc = 0.f;
    #pragma unroll
    for (int k = 0; k < 4; ++k) {
        int m = tid * 4 + k;
        float rv = ref[m * L + l];
        cacc += rv * weight[l * M + m];
        keys[k] = rv;
        vals[k] = m;
    }
    #pragma unroll
    for (int o = 16; o; o >>= 1) cacc += __shfl_down_sync(0xffffffffu, cacc, o);
    if ((tid & 31) == 0) red[tid >> 5] = cacc;
    __syncthreads();
    if (tid == 0) {
        float s = 0.f;
        #pragma unroll
        for (int i = 0; i < 8; ++i) s += red[i];
        g_C[l] = s;
    }
    __syncthreads();

    Sorter(sort_tmp).Sort(keys, vals);   // ascending, blocked arrangement
    __syncthreads();

    #pragma unroll
    for (int k = 0; k < 4; ++k) {
        int p = tid * 4 + k;
        w2_sh[vals[k]] = weight[l * M + p];
    }
    __syncthreads();

    float* Arow = g_A + l * N;
    for (int j = tid; j < N; j += 256) Arow[j] = 0.f;
    __syncthreads();

    for (int i = tid; i < M; i += 256) {
        long long num = (long long)(i + 1) * (N + 1);
        int q = (int)(num / (M + 1));
        int r = (int)(num - (long long)q * (M + 1));
        int j = q - 1;
        float tt = (float)((double)r * (1.0 / (double)(M + 1)));
        float w = w2_sh[i];
        Arow[j]     = (1.f - tt) * w;
        Arow[j + 1] = tt * w;
    }
}

// ---------------------------------------------------------------------------
// Kernel B (v6): mma.sync bf16 GEMM with fragment reuse.
// S[b,l,n] = sum_d X[b,n,d] * W[l,d]; 3-term bf16 split in fp32 accum:
//   S = Whi*Xhi + Whi*Xlo + Wlo*Xhi   (Wlo*Xlo dropped: ~2^-16 relative)
// CTA = 128(l) x 64(n), K=128, 96KB smem -> 2 CTAs/SM.
// Loop nest inverted: per k-step load Ahi/Alo/Bhi/Blo fragments ONCE
// (8 ldsm.x4), then 24 mma (3 term-combos) -> mma:ldsm 3:1 (was 2:1).
// ---------------------------------------------------------------------------
__global__ __launch_bounds__(256, 2) void gemm_mma_kernel(const float* __restrict__ X)
{
    extern __shared__ char smem[];
    const uint32_t sb = smem_u32(smem);
    const int tid = threadIdx.x;

    // --- copy pre-swizzled W images (32KB each) ---
    {
        const uint4* srch = reinterpret_cast<const uint4*>(g_Whi_sw);
        const uint4* srcl = reinterpret_cast<const uint4*>(g_Wlo_sw);
        uint4* dsth = reinterpret_cast<uint4*>(smem);
        uint4* dstl = reinterpret_cast<uint4*>(smem + 32768);
        #pragma unroll
        for (int i = 0; i < 8; ++i) {
            dsth[tid + i * 256] = srch[tid + i * 256];
            dstl[tid + i * 256] = srcl[tid + i * 256];
        }
    }

    // --- load X tile (64 rows), split to bf16 hi/lo, store swizzled ---
    const size_t row0 = (size_t)blockIdx.x << 6;   // flattened (b*4096 + n) base
    {
        const int r  = tid >> 2;                   // row 0..63
        const int ch = (tid & 3) << 5;             // column quarter: 0/32/64/96
        const float4* xr = reinterpret_cast<const float4*>(X + (row0 + (size_t)r) * D + ch);
        char* xh = smem + 65536;
        char* xl = smem + 81920;
        const uint32_t rowbase = r * 256;
        const uint32_t xorv = (r & 7) << 4;
        #pragma unroll
        for (int i = 0; i < 8; ++i) {
            float4 v = xr[i];
            __nv_bfloat16 h0 = __float2bfloat16(v.x);
            __nv_bfloat16 h1 = __float2bfloat16(v.y);
            __nv_bfloat16 h2 = __float2bfloat16(v.z);
            __nv_bfloat16 h3 = __float2bfloat16(v.w);
            __nv_bfloat16 l0 = __float2bfloat16(v.x - __bfloat162float(h0));
            __nv_bfloat16 l1 = __float2bfloat16(v.y - __bfloat162float(h1));
            __nv_bfloat16 l2 = __float2bfloat16(v.z - __bfloat162float(h2));
            __nv_bfloat16 l3 = __float2bfloat16(v.w - __bfloat162float(h3));
            uint32_t ha = ((uint32_t)__bfloat16_as_ushort(h1) << 16) | __bfloat16_as_ushort(h0);
            uint32_t hb = ((uint32_t)__bfloat16_as_ushort(h3) << 16) | __bfloat16_as_ushort(h2);
            uint32_t la = ((uint32_t)__bfloat16_as_ushort(l1) << 16) | __bfloat16_as_ushort(l0);
            uint32_t lb = ((uint32_t)__bfloat16_as_ushort(l3) << 16) | __bfloat16_as_ushort(l2);
            int col = ch + i * 4;
            uint32_t off = rowbase + (((uint32_t)(col * 2)) ^ xorv);
            *reinterpret_cast<uint2*>(xh + off) = make_uint2(ha, hb);
            *reinterpret_cast<uint2*>(xl + off) = make_uint2(la, lb);
        }
    }
    __syncthreads();

    // --- warp MMA mainloop: 4(l) x 2(n) warps, warp tile 32x32 ---
    const int w = tid >> 5, lane = tid & 31;
    const int wl = w >> 1;          // 0..3 -> l offset wl*32
    const int wn = w & 1;           // 0..1 -> n offset wn*32
    const int laneRow = lane & 15;
    const int laneCol = (lane >> 4) << 3;

    // fragment smem addresses (row component fixed per warp)
    const uint32_t Ahi = sb;
    const uint32_t Alo = sb + 32768u;
    const uint32_t Bhi = sb + 65536u;
    const uint32_t Blo = sb + 81920u;
    const int arow0 = wl * 32 + laneRow;        // A frag rows: +0, +16
    const int brow0 = wn * 32 + laneRow;        // B frag rows: +0, +16

    float c[2][4][4];
    #pragma unroll
    for (int i = 0; i < 2; ++i)
        #pragma unroll
        for (int j = 0; j < 4; ++j)
            #pragma unroll
            for (int q = 0; q < 4; ++q) c[i][j][q] = 0.f;

    #pragma unroll 2
    for (int k8 = 0; k8 < 8; ++k8) {
        const int kc = k8 * 16 + laneCol;

        uint32_t ah[2][4], al[2][4];
        #pragma unroll
        for (int mf = 0; mf < 2; ++mf) {
            ldsm4(ah[mf], Ahi + swz(arow0 + mf * 16, kc));
            ldsm4(al[mf], Alo + swz(arow0 + mf * 16, kc));
        }

        uint32_t bh[4][2], bl[4][2];
        #pragma unroll
        for (int p = 0; p < 2; ++p) {
            uint32_t q[4];
            ldsm4(q, Bhi + swz(brow0 + p * 16, kc));
            bh[2 * p][0] = q[0]; bh[2 * p][1] = q[2];
            bh[2 * p + 1][0] = q[1]; bh[2 * p + 1][1] = q[3];
            ldsm4(q, Blo + swz(brow0 + p * 16, kc));
            bl[2 * p][0] = q[0]; bl[2 * p][1] = q[2];
            bl[2 * p + 1][0] = q[1]; bl[2 * p + 1][1] = q[3];
        }

        // 3 split terms, all into the same fp32 accumulators
        #pragma unroll
        for (int mf = 0; mf < 2; ++mf)
            #pragma unroll
            for (int nf = 0; nf < 4; ++nf) {
                mma16816(c[mf][nf], ah[mf], bh[nf]);   // Whi*Xhi
                mma16816(c[mf][nf], ah[mf], bl[nf]);   // Whi*Xlo
                mma16816(c[mf][nf], al[mf], bh[nf]);   // Wlo*Xhi
            }
    }

    // --- epilogue ---
    const int bb = (int)(row0 >> 12);
    const int n0 = (int)(row0 & (N - 1));
    const int rr = lane >> 2;
    const int cg = (lane & 3) << 1;
    #pragma unroll
    for (int mf = 0; mf < 2; ++mf) {
        const int l0 = wl * 32 + mf * 16 + rr;
        float* base0 = g_S + (((size_t)(bb * L + l0)) << 12);
        float* base1 = g_S + (((size_t)(bb * L + l0 + 8)) << 12);
        #pragma unroll
        for (int nf = 0; nf < 4; ++nf) {
            const int n = n0 + wn * 32 + nf * 8 + cg;
            *reinterpret_cast<float2*>(base0 + n) = make_float2(c[mf][nf][0], c[mf][nf][1]);
            *reinterpret_cast<float2*>(base1 + n) = make_float2(c[mf][nf][2], c[mf][nf][3]);
        }
    }
}

// ---------------------------------------------------------------------------
// Kernel C (v9): per-element rescan at 3 CTAs/SM (unchanged from R11).
// ---------------------------------------------------------------------------
#define SORT_SMEM ((N + N + NBUCKET) * 4)   // 48KB

__global__ __launch_bounds__(512, 3) void sortdot_kernel(float* __restrict__ out)
{
    const int l = blockIdx.x >> 6;
    const int b = blockIdx.x & (B - 1);
    const int tid = threadIdx.x;
    const int lane = tid & 31;
    const int wid = tid >> 5;

    extern __shared__ char sds[];
    float* Asm  = reinterpret_cast<float*>(sds);          // N floats
    float* skey = Asm + N;                                // N floats
    int*   hist = reinterpret_cast<int*>(skey + N);       // NBUCKET ints

    __shared__ float redf[16];
    __shared__ float redg[16];
    __shared__ int   reds[16];
    __shared__ float s_mn, s_scale;

    const float* row = g_S + (((size_t)(b * L + l)) << 12);
    float k[8];
    {
        float4 v0 = *reinterpret_cast<const float4*>(row + tid * 8);
        float4 v1 = *reinterpret_cast<const float4*>(row + tid * 8 + 4);
        k[0] = v0.x; k[1] = v0.y; k[2] = v0.z; k[3] = v0.w;
        k[4] = v1.x; k[5] = v1.y; k[6] = v1.z; k[7] = v1.w;
    }
    {
        const float4* Ag = reinterpret_cast<const float4*>(g_A + l * N);
        *reinterpret_cast<float4*>(&Asm[tid * 8])     = Ag[tid * 2];
        *reinterpret_cast<float4*>(&Asm[tid * 8 + 4]) = Ag[tid * 2 + 1];
    }
    {   // zero histogram: 2 x int4 per thread
        int4* h4 = reinterpret_cast<int4*>(hist);
        h4[tid]       = make_int4(0, 0, 0, 0);
        h4[tid + 512] = make_int4(0, 0, 0, 0);
    }

    // --- block min/max (warp shfl + 16-lane combine) ---
    float mn = k[0], mx = k[0];
    #pragma unroll
    for (int i = 1; i < 8; ++i) { mn = fminf(mn, k[i]); mx = fmaxf(mx, k[i]); }
    #pragma unroll
    for (int o = 16; o; o >>= 1) {
        mn = fminf(mn, __shfl_xor_sync(0xffffffffu, mn, o));
        mx = fmaxf(mx, __shfl_xor_sync(0xffffffffu, mx, o));
    }
    if (lane == 0) { redf[wid] = mn; redg[wid] = mx; }
    __syncthreads();
    if (tid < 16) {
        float a = redf[tid], c2 = redg[tid];
        #pragma unroll
        for (int o = 8; o; o >>= 1) {
            a  = fminf(a,  __shfl_xor_sync(0x0000ffffu, a,  o));
            c2 = fmaxf(c2, __shfl_xor_sync(0x0000ffffu, c2, o));
        }
        if (tid == 0) {
            s_mn = a;
            float range = c2 - a;
            s_scale = (range > 0.f) ? ((float)(NBUCKET - 1) / range) : 0.f;
        }
    }
    __syncthreads();

    // --- (1) single atomic pass: histogram + arrival order ---
    const float mn0 = s_mn, scale = s_scale;
    int qq[8];
    int word[8];                      // holds bucket id now; packed word later
    #pragma unroll
    for (int i = 0; i < 8; ++i) {
        int bb2 = (int)((k[i] - mn0) * scale);
        word[i] = min(max(bb2, 0), NBUCKET - 1);
        qq[i] = atomicAdd(&hist[word[i]], 1);
    }
    __syncthreads();

    // --- (2) exclusive prefix sum; packed start | (cnt<<16); int4 access ---
    {
        int4* h4 = reinterpret_cast<int4*>(hist);
        int4 ha = h4[tid * 2];
        int4 hb = h4[tid * 2 + 1];
        int s = ha.x + ha.y + ha.z + ha.w + hb.x + hb.y + hb.z + hb.w;
        int inc = s;
        #pragma unroll
        for (int o = 1; o < 32; o <<= 1) {
            int t = __shfl_up_sync(0xffffffffu, inc, o);
            if (lane >= o) inc += t;
        }
        if (lane == 31) reds[wid] = inc;    // warp totals (inclusive)
        __syncthreads();
        if (tid < 16) {                      // 16-lane exclusive scan of warp totals
            int x = reds[tid];
            int y = x;
            #pragma unroll
            for (int o = 1; o < 16; o <<= 1) {
                int t = __shfl_up_sync(0x0000ffffu, y, o);
                if (tid >= o) y += t;
            }
            reds[tid] = y - x;               // exclusive
        }
        __syncthreads();
        int base = inc - s + reds[wid];
        int4 oa, ob;
        oa.x = base | (ha.x << 16); base += ha.x;
        oa.y = base | (ha.y << 16); base += ha.y;
        oa.z = base | (ha.z << 16); base += ha.z;
        oa.w = base | (ha.w << 16); base += ha.w;
        ob.x = base | (hb.x << 16); base += hb.x;
        ob.y = base | (hb.y << 16); base += hb.y;
        ob.z = base | (hb.z << 16); base += hb.z;
        ob.w = base | (hb.w << 16);
        h4[tid * 2]     = oa;
        h4[tid * 2 + 1] = ob;
        __syncthreads();
    }

    // --- (3) scatter; replace bucket id with packed word (bk dead after) ---
    #pragma unroll
    for (int i = 0; i < 8; ++i) {
        word[i] = hist[word[i]];
        if ((word[i] >> 16) > 1) skey[(word[i] & 0xFFFF) + qq[i]] = k[i];
    }
    __syncthreads();

    // --- (4) rank + fused dot (pos recomputed; cnt==1 fast path) ---
    float acc = 0.f;
    #pragma unroll
    for (int i = 0; i < 8; ++i) {
        const float v = k[i];
        const int start = word[i] & 0xFFFF;
        const int cnt = word[i] >> 16;
        int r = start;
        if (cnt > 1) {
            const int p = start + qq[i];
            const int end = start + cnt;
            for (int q = start; q < end; ++q) {
                float u = skey[q];
                r += (u < v) || (u == v && q < p);
            }
        }
        acc += v * Asm[r];
    }

    #pragma unroll
    for (int o = 16; o; o >>= 1) acc += __shfl_down_sync(0xffffffffu, acc, o);
    if (lane == 0) redf[wid] = acc;
    __syncthreads();
    if (tid < 16) {
        float s = redf[tid];
        #pragma unroll
        for (int o = 8; o; o >>= 1) s += __shfl_xor_sync(0x0000ffffu, s, o);
        if (tid == 0) out[b * L + l] = g_C[l] - s;
    }
}

// ---------------------------------------------------------------------------
extern "C" void kernel_launch(void* const* d_in, const int* in_sizes, int n_in,
                              void* d_out, int out_size)
{
    const float* X       = (const float*)d_in[0];   // [B, N, D]
    const float* theta_v = (const float*)d_in[1];   // [L, D]
    const float* ref     = (const float*)d_in[2];   // [M, L]
    const float* weight  = (const float*)d_in[3];   // [L, M]
    float* out = (float*)d_out;                     // [B, L]

    static bool attr_set = false;
    if (!attr_set) {
        cudaFuncSetAttribute(gemm_mma_kernel,
                             cudaFuncAttributeMaxDynamicSharedMemorySize, GEMM_SMEM);
        cudaFuncSetAttribute(sortdot_kernel,
                             cudaFuncAttributeMaxDynamicSharedMemorySize, SORT_SMEM);
        attr_set = true;
    }

    noop_kernel<<<1, 32>>>();   // two noops: absolute launch index 3 -> gemm
    noop_kernel<<<1, 32>>>();
    precompute_kernel<<<L, 256>>>(theta_v, ref, weight);
    gemm_mma_kernel<<<(B * N) / 64, 256, GEMM_SMEM>>>(X);
    sortdot_kernel<<<B * L, 512, SORT_SMEM>>>(out);
}

// round 13
// speedup vs baseline: 1.1048x; 1.0616x over previous
#include <cuda_runtime.h>
#include <cuda_bf16.h>
#include <cub/block/block_radix_sort.cuh>
#include <cstdint>

#define B 64
#define N 4096
#define D 128
#define M 1024
#define L 128
#define NBUCKET 4096

// Scratch (device globals — no runtime allocation allowed)
__device__ float g_S[(size_t)B * L * N];          // 128 MB slices [B, L, N]
__device__ float g_A[L * N];                      // coefficient vectors
__device__ float g_C[L];                          // constants
__device__ __nv_bfloat16 g_Whi_sw[L * D];         // W hi split, pre-swizzled [l][k] image
__device__ __nv_bfloat16 g_Wlo_sw[L * D];         // W lo split, same layout

// ---------------------------------------------------------------------------
// helpers
// ---------------------------------------------------------------------------
__device__ __forceinline__ uint32_t smem_u32(const void* p) {
    uint32_t a;
    asm("{ .reg .u64 t; cvta.to.shared.u64 t, %1; cvt.u32.u64 %0, t; }" : "=r"(a) : "l"(p));
    return a;
}

// XOR swizzle for a [row][128 bf16] image (256B rows): 16B units XORed by row&7
__device__ __forceinline__ uint32_t swz(int row, int col) {
    return (uint32_t)(row * 256) + (((uint32_t)(col * 2)) ^ (uint32_t)((row & 7) << 4));
}

__device__ __forceinline__ void ldsm4(uint32_t* r, uint32_t addr) {
    asm volatile("ldmatrix.sync.aligned.m8n8.x4.shared.b16 {%0,%1,%2,%3}, [%4];"
                 : "=r"(r[0]), "=r"(r[1]), "=r"(r[2]), "=r"(r[3]) : "r"(addr));
}

__device__ __forceinline__ void mma16816(float* c, const uint32_t* a, const uint32_t* b) {
    asm volatile(
        "mma.sync.aligned.m16n8k16.row.col.f32.bf16.bf16.f32 "
        "{%0,%1,%2,%3}, {%4,%5,%6,%7}, {%8,%9}, {%0,%1,%2,%3};"
        : "+f"(c[0]), "+f"(c[1]), "+f"(c[2]), "+f"(c[3])
        : "r"(a[0]), "r"(a[1]), "r"(a[2]), "r"(a[3]), "r"(b[0]), "r"(b[1]));
}

// GEMM smem: Whi@0(32K), Wlo@32K, Xhi@64K(32K), Xlo@96K(32K) = 128KB
#define GEMM_SMEM 131072

// Dummy no-op kernels: position the ncu profile window (absolute launch
// index 3) onto gemm_mma_kernel. <1us each.
__global__ void noop_kernel() {}

// ---------------------------------------------------------------------------
// Kernel A: per-l precompute. Normalize W -> bf16 hi/lo (pre-swizzled images),
// constant C, ref argsort folded with interp stencil into dense a[l, 0..N).
// ---------------------------------------------------------------------------
__global__ __launch_bounds__(256) void precompute_kernel(
    const float* __restrict__ theta_v,
    const float* __restrict__ ref,
    const float* __restrict__ weight)
{
    const int l = blockIdx.x;
    const int tid = threadIdx.x;

    typedef cub::BlockRadixSort<float, 256, 4, int> Sorter;
    __shared__ typename Sorter::TempStorage sort_tmp;
    __shared__ float red[8];
    __shared__ float w2_sh[M];

    // --- normalize theta row ---
    float tv = (tid < D) ? theta_v[l * D + tid] : 0.f;
    float ss = tv * tv;
    #pragma unroll
    for (int o = 16; o; o >>= 1) ss += __shfl_down_sync(0xffffffffu, ss, o);
    if ((tid & 31) == 0) red[tid >> 5] = ss;
    __syncthreads();
    if (tid == 0) {
        float s = 0.f;
        #pragma unroll
        for (int i = 0; i < 8; ++i) s += red[i];
        red[0] = s;
    }
    __syncthreads();
    {
        float nrm = sqrtf(red[0]);
        if (tid < D) {
            float wv = tv / nrm;
            __nv_bfloat16 h = __float2bfloat16(wv);
            __nv_bfloat16 lo = __float2bfloat16(wv - __bfloat162float(h));
            uint32_t sw = swz(l, tid);
            g_Whi_sw[sw >> 1] = h;
            g_Wlo_sw[sw >> 1] = lo;
        }
    }
    __syncthreads();  // red reused below

    // --- C[l] and sort keys ---
    float keys[4]; int vals[4];
    float cacc = 0.f;
    #pragma unroll
    for (int k = 0; k < 4; ++k) {
        int m = tid * 4 + k;
        float rv = ref[m * L + l];
        cacc += rv * weight[l * M + m];
        keys[k] = rv;
        vals[k] = m;
    }
    #pragma unroll
    for (int o = 16; o; o >>= 1) cacc += __shfl_down_sync(0xffffffffu, cacc, o);
    if ((tid & 31) == 0) red[tid >> 5] = cacc;
    __syncthreads();
    if (tid == 0) {
        float s = 0.f;
        #pragma unroll
        for (int i = 0; i < 8; ++i) s += red[i];
        g_C[l] = s;
    }
    __syncthreads();

    Sorter(sort_tmp).Sort(keys, vals);   // ascending, blocked arrangement
    __syncthreads();

    #pragma unroll
    for (int k = 0; k < 4; ++k) {
        int p = tid * 4 + k;
        w2_sh[vals[k]] = weight[l * M + p];
    }
    __syncthreads();

    float* Arow = g_A + l * N;
    for (int j = tid; j < N; j += 256) Arow[j] = 0.f;
    __syncthreads();

    for (int i = tid; i < M; i += 256) {
        long long num = (long long)(i + 1) * (N + 1);
        int q = (int)(num / (M + 1));
        int r = (int)(num - (long long)q * (M + 1));
        int j = q - 1;
        float tt = (float)((double)r * (1.0 / (double)(M + 1)));
        float w = w2_sh[i];
        Arow[j]     = (1.f - tt) * w;
        Arow[j + 1] = tt * w;
    }
}

// ---------------------------------------------------------------------------
// Kernel B (v7): mma.sync bf16 GEMM, 128x128 CTA tile, fragment reuse.
// S[b,l,n] = sum_d X[b,n,d] * W[l,d]; 3-term bf16 split in fp32 accum:
//   S = Whi*Xhi + Whi*Xlo + Wlo*Xhi   (Wlo*Xlo dropped: ~2^-16 relative)
// CTA = 128(l) x 128(n), K=128, 128KB smem -> 1 CTA/SM.
// 8 warps in 2(l) x 4(n) grid; warp tile 64 x 32.
// Per k-step: 12 ldsm.x4 (Ahi4+Alo4+Bhi2+Blo2), 48 mma -> mma:ldsm 4:1.
// W copy amortized over 2x work vs the 128x64 tile.
// ---------------------------------------------------------------------------
__global__ __launch_bounds__(256, 1) void gemm_mma_kernel(const float* __restrict__ X)
{
    extern __shared__ char smem[];
    const uint32_t sb = smem_u32(smem);
    const int tid = threadIdx.x;

    // --- copy pre-swizzled W images (32KB each) ---
    {
        const uint4* srch = reinterpret_cast<const uint4*>(g_Whi_sw);
        const uint4* srcl = reinterpret_cast<const uint4*>(g_Wlo_sw);
        uint4* dsth = reinterpret_cast<uint4*>(smem);
        uint4* dstl = reinterpret_cast<uint4*>(smem + 32768);
        #pragma unroll
        for (int i = 0; i < 8; ++i) {
            dsth[tid + i * 256] = srch[tid + i * 256];
            dstl[tid + i * 256] = srcl[tid + i * 256];
        }
    }

    // --- load X tile (128 rows), split to bf16 hi/lo, store swizzled ---
    const size_t row0 = (size_t)blockIdx.x << 7;   // flattened (b*4096 + n) base
    {
        const int r  = tid >> 1;                   // row 0..127
        const int ch = (tid & 1) << 6;             // column half: 0 or 64
        const float4* xr = reinterpret_cast<const float4*>(X + (row0 + (size_t)r) * D + ch);
        char* xh = smem + 65536;
        char* xl = smem + 98304;
        const uint32_t rowbase = r * 256;
        const uint32_t xorv = (r & 7) << 4;
        #pragma unroll
        for (int i = 0; i < 16; ++i) {
            float4 v = xr[i];
            __nv_bfloat16 h0 = __float2bfloat16(v.x);
            __nv_bfloat16 h1 = __float2bfloat16(v.y);
            __nv_bfloat16 h2 = __float2bfloat16(v.z);
            __nv_bfloat16 h3 = __float2bfloat16(v.w);
            __nv_bfloat16 l0 = __float2bfloat16(v.x - __bfloat162float(h0));
            __nv_bfloat16 l1 = __float2bfloat16(v.y - __bfloat162float(h1));
            __nv_bfloat16 l2 = __float2bfloat16(v.z - __bfloat162float(h2));
            __nv_bfloat16 l3 = __float2bfloat16(v.w - __bfloat162float(h3));
            uint32_t ha = ((uint32_t)__bfloat16_as_ushort(h1) << 16) | __bfloat16_as_ushort(h0);
            uint32_t hb = ((uint32_t)__bfloat16_as_ushort(h3) << 16) | __bfloat16_as_ushort(h2);
            uint32_t la = ((uint32_t)__bfloat16_as_ushort(l1) << 16) | __bfloat16_as_ushort(l0);
            uint32_t lb = ((uint32_t)__bfloat16_as_ushort(l3) << 16) | __bfloat16_as_ushort(l2);
            int col = ch + i * 4;
            uint32_t off = rowbase + (((uint32_t)(col * 2)) ^ xorv);
            *reinterpret_cast<uint2*>(xh + off) = make_uint2(ha, hb);
            *reinterpret_cast<uint2*>(xl + off) = make_uint2(la, lb);
        }
    }
    __syncthreads();

    // --- warp MMA mainloop: 2(l) x 4(n) warps, warp tile 64x32 ---
    const int w = tid >> 5, lane = tid & 31;
    const int wl = w >> 2;          // 0..1 -> l offset wl*64
    const int wn = w & 3;           // 0..3 -> n offset wn*32
    const int laneRow = lane & 15;
    const int laneCol = (lane >> 4) << 3;

    const uint32_t Ahi = sb;
    const uint32_t Alo = sb + 32768u;
    const uint32_t Bhi = sb + 65536u;
    const uint32_t Blo = sb + 98304u;
    const int arow0 = wl * 64 + laneRow;        // A frag rows: +0,16,32,48
    const int brow0 = wn * 32 + laneRow;        // B frag rows: +0, +16

    float c[4][4][4];
    #pragma unroll
    for (int i = 0; i < 4; ++i)
        #pragma unroll
        for (int j = 0; j < 4; ++j)
            #pragma unroll
            for (int q = 0; q < 4; ++q) c[i][j][q] = 0.f;

    #pragma unroll 1
    for (int k8 = 0; k8 < 8; ++k8) {
        const int kc = k8 * 16 + laneCol;

        uint32_t ah[4][4], al[4][4];
        #pragma unroll
        for (int mf = 0; mf < 4; ++mf) {
            ldsm4(ah[mf], Ahi + swz(arow0 + mf * 16, kc));
            ldsm4(al[mf], Alo + swz(arow0 + mf * 16, kc));
        }

        uint32_t bh[4][2], bl[4][2];
        #pragma unroll
        for (int p = 0; p < 2; ++p) {
            uint32_t q[4];
            ldsm4(q, Bhi + swz(brow0 + p * 16, kc));
            bh[2 * p][0] = q[0]; bh[2 * p][1] = q[2];
            bh[2 * p + 1][0] = q[1]; bh[2 * p + 1][1] = q[3];
            ldsm4(q, Blo + swz(brow0 + p * 16, kc));
            bl[2 * p][0] = q[0]; bl[2 * p][1] = q[2];
            bl[2 * p + 1][0] = q[1]; bl[2 * p + 1][1] = q[3];
        }

        // 3 split terms, all into the same fp32 accumulators
        #pragma unroll
        for (int mf = 0; mf < 4; ++mf)
            #pragma unroll
            for (int nf = 0; nf < 4; ++nf) {
                mma16816(c[mf][nf], ah[mf], bh[nf]);   // Whi*Xhi
                mma16816(c[mf][nf], ah[mf], bl[nf]);   // Whi*Xlo
                mma16816(c[mf][nf], al[mf], bh[nf]);   // Wlo*Xhi
            }
    }

    // --- epilogue ---
    const int bb = (int)(row0 >> 12);
    const int n0 = (int)(row0 & (N - 1));
    const int rr = lane >> 2;
    const int cg = (lane & 3) << 1;
    #pragma unroll
    for (int mf = 0; mf < 4; ++mf) {
        const int l0 = wl * 64 + mf * 16 + rr;
        float* base0 = g_S + (((size_t)(bb * L + l0)) << 12);
        float* base1 = g_S + (((size_t)(bb * L + l0 + 8)) << 12);
        #pragma unroll
        for (int nf = 0; nf < 4; ++nf) {
            const int n = n0 + wn * 32 + nf * 8 + cg;
            *reinterpret_cast<float2*>(base0 + n) = make_float2(c[mf][nf][0], c[mf][nf][1]);
            *reinterpret_cast<float2*>(base1 + n) = make_float2(c[mf][nf][2], c[mf][nf][3]);
        }
    }
}

// ---------------------------------------------------------------------------
// Kernel C (v10): per-element rescan at 3 CTAs/SM with LOGISTIC quantile
// bucketing: bk = 4096*sigmoid(1.6*v). Slice values are exactly N(0,1)
// (X iid normal, |W|=1), so this gives lambda ~= 1 in every bucket (the old
// value-uniform map had lambda ~= 3 at the center). Fixed map -> the min/max
// reduction phase is gone. Any <=2ulp non-monotonicity in __expf can only
// swap ranks of near-equal values: error ~ (v1-v2)*(a_i-a_j) ~ 1e-10.
// ---------------------------------------------------------------------------
#define SORT_SMEM ((N + N + NBUCKET) * 4)   // 48KB

__global__ __launch_bounds__(512, 3) void sortdot_kernel(float* __restrict__ out)
{
    const int l = blockIdx.x >> 6;
    const int b = blockIdx.x & (B - 1);
    const int tid = threadIdx.x;
    const int lane = tid & 31;
    const int wid = tid >> 5;

    extern __shared__ char sds[];
    float* Asm  = reinterpret_cast<float*>(sds);          // N floats
    float* skey = Asm + N;                                // N floats
    int*   hist = reinterpret_cast<int*>(skey + N);       // NBUCKET ints

    __shared__ float redf[16];
    __shared__ int   reds[16];

    const float* row = g_S + (((size_t)(b * L + l)) << 12);
    float k[8];
    {
        float4 v0 = *reinterpret_cast<const float4*>(row + tid * 8);
        float4 v1 = *reinterpret_cast<const float4*>(row + tid * 8 + 4);
        k[0] = v0.x; k[1] = v0.y; k[2] = v0.z; k[3] = v0.w;
        k[4] = v1.x; k[5] = v1.y; k[6] = v1.z; k[7] = v1.w;
    }
    {
        const float4* Ag = reinterpret_cast<const float4*>(g_A + l * N);
        *reinterpret_cast<float4*>(&Asm[tid * 8])     = Ag[tid * 2];
        *reinterpret_cast<float4*>(&Asm[tid * 8 + 4]) = Ag[tid * 2 + 1];
    }
    {   // zero histogram: 2 x int4 per thread
        int4* h4 = reinterpret_cast<int4*>(hist);
        h4[tid]       = make_int4(0, 0, 0, 0);
        h4[tid + 512] = make_int4(0, 0, 0, 0);
    }
    __syncthreads();

    // --- (1) single atomic pass: logistic bucket + histogram + arrival ---
    int qq[8];
    int word[8];                      // holds bucket id now; packed word later
    #pragma unroll
    for (int i = 0; i < 8; ++i) {
        float e = __expf(-1.6f * k[i]);
        int bb2 = (int)(__fdividef(4096.0f, 1.0f + e));
        word[i] = min(max(bb2, 0), NBUCKET - 1);
        qq[i] = atomicAdd(&hist[word[i]], 1);
    }
    __syncthreads();

    // --- (2) exclusive prefix sum; packed start | (cnt<<16); int4 access ---
    {
        int4* h4 = reinterpret_cast<int4*>(hist);
        int4 ha = h4[tid * 2];
        int4 hb = h4[tid * 2 + 1];
        int s = ha.x + ha.y + ha.z + ha.w + hb.x + hb.y + hb.z + hb.w;
        int inc = s;
        #pragma unroll
        for (int o = 1; o < 32; o <<= 1) {
            int t = __shfl_up_sync(0xffffffffu, inc, o);
            if (lane >= o) inc += t;
        }
        if (lane == 31) reds[wid] = inc;    // warp totals (inclusive)
        __syncthreads();
        if (tid < 16) {                      // 16-lane exclusive scan of warp totals
            int x = reds[tid];
            int y = x;
            #pragma unroll
            for (int o = 1; o < 16; o <<= 1) {
                int t = __shfl_up_sync(0x0000ffffu, y, o);
                if (tid >= o) y += t;
            }
            reds[tid] = y - x;               // exclusive
        }
        __syncthreads();
        int base = inc - s + reds[wid];
        int4 oa, ob;
        oa.x = base | (ha.x << 16); base += ha.x;
        oa.y = base | (ha.y << 16); base += ha.y;
        oa.z = base | (ha.z << 16); base += ha.z;
        oa.w = base | (ha.w << 16); base += ha.w;
        ob.x = base | (hb.x << 16); base += hb.x;
        ob.y = base | (hb.y << 16); base += hb.y;
        ob.z = base | (hb.z << 16); base += hb.z;
        ob.w = base | (hb.w << 16);
        h4[tid * 2]     = oa;
        h4[tid * 2 + 1] = ob;
        __syncthreads();
    }

    // --- (3) scatter; replace bucket id with packed word (bk dead after) ---
    #pragma unroll
    for (int i = 0; i < 8; ++i) {
        word[i] = hist[word[i]];
        if ((word[i] >> 16) > 1) skey[(word[i] & 0xFFFF) + qq[i]] = k[i];
    }
    __syncthreads();

    // --- (4) rank + fused dot (pos recomputed; cnt==1 fast path) ---
    float acc = 0.f;
    #pragma unroll
    for (int i = 0; i < 8; ++i) {
        const float v = k[i];
        const int start = word[i] & 0xFFFF;
        const int cnt = word[i] >> 16;
        int r = start;
        if (cnt > 1) {
            const int p = start + qq[i];
            const int end = start + cnt;
            for (int q = start; q < end; ++q) {
                float u = skey[q];
                r += (u < v) || (u == v && q < p);
            }
        }
        acc += v * Asm[r];
    }

    #pragma unroll
    for (int o = 16; o; o >>= 1) acc += __shfl_down_sync(0xffffffffu, acc, o);
    if (lane == 0) redf[wid] = acc;
    __syncthreads();
    if (tid < 16) {
        float s = redf[tid];
        #pragma unroll
        for (int o = 8; o; o >>= 1) s += __shfl_xor_sync(0x0000ffffu, s, o);
        if (tid == 0) out[b * L + l] = g_C[l] - s;
    }
}

// ---------------------------------------------------------------------------
extern "C" void kernel_launch(void* const* d_in, const int* in_sizes, int n_in,
                              void* d_out, int out_size)
{
    const float* X       = (const float*)d_in[0];   // [B, N, D]
    const float* theta_v = (const float*)d_in[1];   // [L, D]
    const float* ref     = (const float*)d_in[2];   // [M, L]
    const float* weight  = (const float*)d_in[3];   // [L, M]
    float* out = (float*)d_out;                     // [B, L]

    static bool attr_set = false;
    if (!attr_set) {
        cudaFuncSetAttribute(gemm_mma_kernel,
                             cudaFuncAttributeMaxDynamicSharedMemorySize, GEMM_SMEM);
        cudaFuncSetAttribute(sortdot_kernel,
                             cudaFuncAttributeMaxDynamicSharedMemorySize, SORT_SMEM);
        attr_set = true;
    }

    noop_kernel<<<1, 32>>>();   // two noops: absolute launch index 3 -> gemm
    noop_kernel<<<1, 32>>>();
    precompute_kernel<<<L, 256>>>(theta_v, ref, weight);
    gemm_mma_kernel<<<(B * N) / 128, 256, GEMM_SMEM>>>(X);
    sortdot_kernel<<<B * L, 512, SORT_SMEM>>>(out);
}

// round 14
// speedup vs baseline: 1.1709x; 1.0598x over previous
#include <cuda_runtime.h>
#include <cuda_bf16.h>
#include <cub/block/block_radix_sort.cuh>
#include <cstdint>

#define B 64
#define N 4096
#define D 128
#define M 1024
#define L 128
#define NBUCKET 4096

// Scratch (device globals — no runtime allocation allowed)
__device__ float g_S[(size_t)B * L * N];          // 128 MB slices [B, L, N]
__device__ float g_A[L * N];                      // coefficient vectors
__device__ float g_C[L];                          // constants
__device__ __nv_bfloat16 g_Whi_sw[L * D];         // W hi split, pre-swizzled [l][k] image
__device__ __nv_bfloat16 g_Wlo_sw[L * D];         // W lo split, same layout

// ---------------------------------------------------------------------------
// helpers
// ---------------------------------------------------------------------------
__device__ __forceinline__ uint32_t smem_u32(const void* p) {
    uint32_t a;
    asm("{ .reg .u64 t; cvta.to.shared.u64 t, %1; cvt.u32.u64 %0, t; }" : "=r"(a) : "l"(p));
    return a;
}

// XOR swizzle for a [row][128 bf16] image (256B rows): 16B units XORed by row&7
__device__ __forceinline__ uint32_t swz(int row, int col) {
    return (uint32_t)(row * 256) + (((uint32_t)(col * 2)) ^ (uint32_t)((row & 7) << 4));
}

__device__ __forceinline__ void ldsm4(uint32_t* r, uint32_t addr) {
    asm volatile("ldmatrix.sync.aligned.m8n8.x4.shared.b16 {%0,%1,%2,%3}, [%4];"
                 : "=r"(r[0]), "=r"(r[1]), "=r"(r[2]), "=r"(r[3]) : "r"(addr));
}

__device__ __forceinline__ void mma16816(float* c, const uint32_t* a, const uint32_t* b) {
    asm volatile(
        "mma.sync.aligned.m16n8k16.row.col.f32.bf16.bf16.f32 "
        "{%0,%1,%2,%3}, {%4,%5,%6,%7}, {%8,%9}, {%0,%1,%2,%3};"
        : "+f"(c[0]), "+f"(c[1]), "+f"(c[2]), "+f"(c[3])
        : "r"(a[0]), "r"(a[1]), "r"(a[2]), "r"(a[3]), "r"(b[0]), "r"(b[1]));
}

// GEMM smem: Whi@0(32K), Wlo@32K, Xhi@64K(16K), Xlo@80K(16K) = 96KB
#define GEMM_SMEM 98304

// Dummy no-op kernels: position the ncu profile window (absolute launch
// index 3) onto gemm_mma_kernel. <1us each.
__global__ void noop_kernel() {}

// ---------------------------------------------------------------------------
// Kernel A: per-l precompute. Normalize W -> bf16 hi/lo (pre-swizzled images),
// constant C, ref argsort folded with interp stencil into dense a[l, 0..N).
// ---------------------------------------------------------------------------
__global__ __launch_bounds__(256) void precompute_kernel(
    const float* __restrict__ theta_v,
    const float* __restrict__ ref,
    const float* __restrict__ weight)
{
    const int l = blockIdx.x;
    const int tid = threadIdx.x;

    typedef cub::BlockRadixSort<float, 256, 4, int> Sorter;
    __shared__ typename Sorter::TempStorage sort_tmp;
    __shared__ float red[8];
    __shared__ float w2_sh[M];

    // --- normalize theta row ---
    float tv = (tid < D) ? theta_v[l * D + tid] : 0.f;
    float ss = tv * tv;
    #pragma unroll
    for (int o = 16; o; o >>= 1) ss += __shfl_down_sync(0xffffffffu, ss, o);
    if ((tid & 31) == 0) red[tid >> 5] = ss;
    __syncthreads();
    if (tid == 0) {
        float s = 0.f;
        #pragma unroll
        for (int i = 0; i < 8; ++i) s += red[i];
        red[0] = s;
    }
    __syncthreads();
    {
        float nrm = sqrtf(red[0]);
        if (tid < D) {
            float wv = tv / nrm;
            __nv_bfloat16 h = __float2bfloat16(wv);
            __nv_bfloat16 lo = __float2bfloat16(wv - __bfloat162float(h));
            uint32_t sw = swz(l, tid);
            g_Whi_sw[sw >> 1] = h;
            g_Wlo_sw[sw >> 1] = lo;
        }
    }
    __syncthreads();  // red reused below

    // --- C[l] and sort keys ---
    float keys[4]; int vals[4];
    float cacc = 0.f;
    #pragma unroll
    for (int k = 0; k < 4; ++k) {
        int m = tid * 4 + k;
        float rv = ref[m * L + l];
        cacc += rv * weight[l * M + m];
        keys[k] = rv;
        vals[k] = m;
    }
    #pragma unroll
    for (int o = 16; o; o >>= 1) cacc += __shfl_down_sync(0xffffffffu, cacc, o);
    if ((tid & 31) == 0) red[tid >> 5] = cacc;
    __syncthreads();
    if (tid == 0) {
        float s = 0.f;
        #pragma unroll
        for (int i = 0; i < 8; ++i) s += red[i];
        g_C[l] = s;
    }
    __syncthreads();

    Sorter(sort_tmp).Sort(keys, vals);   // ascending, blocked arrangement
    __syncthreads();

    #pragma unroll
    for (int k = 0; k < 4; ++k) {
        int p = tid * 4 + k;
        w2_sh[vals[k]] = weight[l * M + p];
    }
    __syncthreads();

    float* Arow = g_A + l * N;
    for (int j = tid; j < N; j += 256) Arow[j] = 0.f;
    __syncthreads();

    for (int i = tid; i < M; i += 256) {
        long long num = (long long)(i + 1) * (N + 1);
        int q = (int)(num / (M + 1));
        int r = (int)(num - (long long)q * (M + 1));
        int j = q - 1;
        float tt = (float)((double)r * (1.0 / (double)(M + 1)));
        float w = w2_sh[i];
        Arow[j]     = (1.f - tt) * w;
        Arow[j + 1] = tt * w;
    }
}

// ---------------------------------------------------------------------------
// Kernel B (R12 config — measured 135.6us): mma.sync bf16 GEMM, fragment
// reuse, CTA = 128(l) x 64(n), K=128, 96KB smem -> 2 CTAs/SM.
// S = Whi*Xhi + Whi*Xlo + Wlo*Xhi   (Wlo*Xlo dropped: ~2^-16 relative)
// 8 warps in 4(l) x 2(n) grid; warp tile 32 x 32; mma:ldsm = 3:1.
// ---------------------------------------------------------------------------
__global__ __launch_bounds__(256, 2) void gemm_mma_kernel(const float* __restrict__ X)
{
    extern __shared__ char smem[];
    const uint32_t sb = smem_u32(smem);
    const int tid = threadIdx.x;

    // --- copy pre-swizzled W images (32KB each) ---
    {
        const uint4* srch = reinterpret_cast<const uint4*>(g_Whi_sw);
        const uint4* srcl = reinterpret_cast<const uint4*>(g_Wlo_sw);
        uint4* dsth = reinterpret_cast<uint4*>(smem);
        uint4* dstl = reinterpret_cast<uint4*>(smem + 32768);
        #pragma unroll
        for (int i = 0; i < 8; ++i) {
            dsth[tid + i * 256] = srch[tid + i * 256];
            dstl[tid + i * 256] = srcl[tid + i * 256];
        }
    }

    // --- load X tile (64 rows), split to bf16 hi/lo, store swizzled ---
    const size_t row0 = (size_t)blockIdx.x << 6;   // flattened (b*4096 + n) base
    {
        const int r  = tid >> 2;                   // row 0..63
        const int ch = (tid & 3) << 5;             // column quarter: 0/32/64/96
        const float4* xr = reinterpret_cast<const float4*>(X + (row0 + (size_t)r) * D + ch);
        char* xh = smem + 65536;
        char* xl = smem + 81920;
        const uint32_t rowbase = r * 256;
        const uint32_t xorv = (r & 7) << 4;
        #pragma unroll
        for (int i = 0; i < 8; ++i) {
            float4 v = xr[i];
            __nv_bfloat16 h0 = __float2bfloat16(v.x);
            __nv_bfloat16 h1 = __float2bfloat16(v.y);
            __nv_bfloat16 h2 = __float2bfloat16(v.z);
            __nv_bfloat16 h3 = __float2bfloat16(v.w);
            __nv_bfloat16 l0 = __float2bfloat16(v.x - __bfloat162float(h0));
            __nv_bfloat16 l1 = __float2bfloat16(v.y - __bfloat162float(h1));
            __nv_bfloat16 l2 = __float2bfloat16(v.z - __bfloat162float(h2));
            __nv_bfloat16 l3 = __float2bfloat16(v.w - __bfloat162float(h3));
            uint32_t ha = ((uint32_t)__bfloat16_as_ushort(h1) << 16) | __bfloat16_as_ushort(h0);
            uint32_t hb = ((uint32_t)__bfloat16_as_ushort(h3) << 16) | __bfloat16_as_ushort(h2);
            uint32_t la = ((uint32_t)__bfloat16_as_ushort(l1) << 16) | __bfloat16_as_ushort(l0);
            uint32_t lb = ((uint32_t)__bfloat16_as_ushort(l3) << 16) | __bfloat16_as_ushort(l2);
            int col = ch + i * 4;
            uint32_t off = rowbase + (((uint32_t)(col * 2)) ^ xorv);
            *reinterpret_cast<uint2*>(xh + off) = make_uint2(ha, hb);
            *reinterpret_cast<uint2*>(xl + off) = make_uint2(la, lb);
        }
    }
    __syncthreads();

    // --- warp MMA mainloop: 4(l) x 2(n) warps, warp tile 32x32 ---
    const int w = tid >> 5, lane = tid & 31;
    const int wl = w >> 1;          // 0..3 -> l offset wl*32
    const int wn = w & 1;           // 0..1 -> n offset wn*32
    const int laneRow = lane & 15;
    const int laneCol = (lane >> 4) << 3;

    const uint32_t Ahi = sb;
    const uint32_t Alo = sb + 32768u;
    const uint32_t Bhi = sb + 65536u;
    const uint32_t Blo = sb + 81920u;
    const int arow0 = wl * 32 + laneRow;        // A frag rows: +0, +16
    const int brow0 = wn * 32 + laneRow;        // B frag rows: +0, +16

    float c[2][4][4];
    #pragma unroll
    for (int i = 0; i < 2; ++i)
        #pragma unroll
        for (int j = 0; j < 4; ++j)
            #pragma unroll
            for (int q = 0; q < 4; ++q) c[i][j][q] = 0.f;

    #pragma unroll 2
    for (int k8 = 0; k8 < 8; ++k8) {
        const int kc = k8 * 16 + laneCol;

        uint32_t ah[2][4], al[2][4];
        #pragma unroll
        for (int mf = 0; mf < 2; ++mf) {
            ldsm4(ah[mf], Ahi + swz(arow0 + mf * 16, kc));
            ldsm4(al[mf], Alo + swz(arow0 + mf * 16, kc));
        }

        uint32_t bh[4][2], bl[4][2];
        #pragma unroll
        for (int p = 0; p < 2; ++p) {
            uint32_t q[4];
            ldsm4(q, Bhi + swz(brow0 + p * 16, kc));
            bh[2 * p][0] = q[0]; bh[2 * p][1] = q[2];
            bh[2 * p + 1][0] = q[1]; bh[2 * p + 1][1] = q[3];
            ldsm4(q, Blo + swz(brow0 + p * 16, kc));
            bl[2 * p][0] = q[0]; bl[2 * p][1] = q[2];
            bl[2 * p + 1][0] = q[1]; bl[2 * p + 1][1] = q[3];
        }

        // 3 split terms, all into the same fp32 accumulators
        #pragma unroll
        for (int mf = 0; mf < 2; ++mf)
            #pragma unroll
            for (int nf = 0; nf < 4; ++nf) {
                mma16816(c[mf][nf], ah[mf], bh[nf]);   // Whi*Xhi
                mma16816(c[mf][nf], ah[mf], bl[nf]);   // Whi*Xlo
                mma16816(c[mf][nf], al[mf], bh[nf]);   // Wlo*Xhi
            }
    }

    // --- epilogue ---
    const int bb = (int)(row0 >> 12);
    const int n0 = (int)(row0 & (N - 1));
    const int rr = lane >> 2;
    const int cg = (lane & 3) << 1;
    #pragma unroll
    for (int mf = 0; mf < 2; ++mf) {
        const int l0 = wl * 32 + mf * 16 + rr;
        float* base0 = g_S + (((size_t)(bb * L + l0)) << 12);
        float* base1 = g_S + (((size_t)(bb * L + l0 + 8)) << 12);
        #pragma unroll
        for (int nf = 0; nf < 4; ++nf) {
            const int n = n0 + wn * 32 + nf * 8 + cg;
            *reinterpret_cast<float2*>(base0 + n) = make_float2(c[mf][nf][0], c[mf][nf][1]);
            *reinterpret_cast<float2*>(base1 + n) = make_float2(c[mf][nf][2], c[mf][nf][3]);
        }
    }
}

// ---------------------------------------------------------------------------
// Kernel C (R13 config — measured ~163us): per-element rescan at 3 CTAs/SM
// with LOGISTIC quantile bucketing: bk = 4096*sigmoid(1.6*v). Slice values
// are N(0,1) (X iid normal, |W|=1) -> lambda ~= 1 uniform across buckets.
// Fixed map, no min/max phase. <=2ulp __expf non-monotonicity only swaps
// near-equal ranks: error ~ (v1-v2)*(a_i-a_j), negligible.
// ---------------------------------------------------------------------------
#define SORT_SMEM ((N + N + NBUCKET) * 4)   // 48KB

__global__ __launch_bounds__(512, 3) void sortdot_kernel(float* __restrict__ out)
{
    const int l = blockIdx.x >> 6;
    const int b = blockIdx.x & (B - 1);
    const int tid = threadIdx.x;
    const int lane = tid & 31;
    const int wid = tid >> 5;

    extern __shared__ char sds[];
    float* Asm  = reinterpret_cast<float*>(sds);          // N floats
    float* skey = Asm + N;                                // N floats
    int*   hist = reinterpret_cast<int*>(skey + N);       // NBUCKET ints

    __shared__ float redf[16];
    __shared__ int   reds[16];

    const float* row = g_S + (((size_t)(b * L + l)) << 12);
    float k[8];
    {
        float4 v0 = *reinterpret_cast<const float4*>(row + tid * 8);
        float4 v1 = *reinterpret_cast<const float4*>(row + tid * 8 + 4);
        k[0] = v0.x; k[1] = v0.y; k[2] = v0.z; k[3] = v0.w;
        k[4] = v1.x; k[5] = v1.y; k[6] = v1.z; k[7] = v1.w;
    }
    {
        const float4* Ag = reinterpret_cast<const float4*>(g_A + l * N);
        *reinterpret_cast<float4*>(&Asm[tid * 8])     = Ag[tid * 2];
        *reinterpret_cast<float4*>(&Asm[tid * 8 + 4]) = Ag[tid * 2 + 1];
    }
    {   // zero histogram: 2 x int4 per thread
        int4* h4 = reinterpret_cast<int4*>(hist);
        h4[tid]       = make_int4(0, 0, 0, 0);
        h4[tid + 512] = make_int4(0, 0, 0, 0);
    }
    __syncthreads();

    // --- (1) single atomic pass: logistic bucket + histogram + arrival ---
    int qq[8];
    int word[8];                      // holds bucket id now; packed word later
    #pragma unroll
    for (int i = 0; i < 8; ++i) {
        float e = __expf(-1.6f * k[i]);
        int bb2 = (int)(__fdividef(4096.0f, 1.0f + e));
        word[i] = min(max(bb2, 0), NBUCKET - 1);
        qq[i] = atomicAdd(&hist[word[i]], 1);
    }
    __syncthreads();

    // --- (2) exclusive prefix sum; packed start | (cnt<<16); int4 access ---
    {
        int4* h4 = reinterpret_cast<int4*>(hist);
        int4 ha = h4[tid * 2];
        int4 hb = h4[tid * 2 + 1];
        int s = ha.x + ha.y + ha.z + ha.w + hb.x + hb.y + hb.z + hb.w;
        int inc = s;
        #pragma unroll
        for (int o = 1; o < 32; o <<= 1) {
            int t = __shfl_up_sync(0xffffffffu, inc, o);
            if (lane >= o) inc += t;
        }
        if (lane == 31) reds[wid] = inc;    // warp totals (inclusive)
        __syncthreads();
        if (tid < 16) {                      // 16-lane exclusive scan of warp totals
            int x = reds[tid];
            int y = x;
            #pragma unroll
            for (int o = 1; o < 16; o <<= 1) {
                int t = __shfl_up_sync(0x0000ffffu, y, o);
                if (tid >= o) y += t;
            }
            reds[tid] = y - x;               // exclusive
        }
        __syncthreads();
        int base = inc - s + reds[wid];
        int4 oa, ob;
        oa.x = base | (ha.x << 16); base += ha.x;
        oa.y = base | (ha.y << 16); base += ha.y;
        oa.z = base | (ha.z << 16); base += ha.z;
        oa.w = base | (ha.w << 16); base += ha.w;
        ob.x = base | (hb.x << 16); base += hb.x;
        ob.y = base | (hb.y << 16); base += hb.y;
        ob.z = base | (hb.z << 16); base += hb.z;
        ob.w = base | (hb.w << 16);
        h4[tid * 2]     = oa;
        h4[tid * 2 + 1] = ob;
        __syncthreads();
    }

    // --- (3) scatter; replace bucket id with packed word (bk dead after) ---
    #pragma unroll
    for (int i = 0; i < 8; ++i) {
        word[i] = hist[word[i]];
        if ((word[i] >> 16) > 1) skey[(word[i] & 0xFFFF) + qq[i]] = k[i];
    }
    __syncthreads();

    // --- (4) rank + fused dot (pos recomputed; cnt==1 fast path) ---
    float acc = 0.f;
    #pragma unroll
    for (int i = 0; i < 8; ++i) {
        const float v = k[i];
        const int start = word[i] & 0xFFFF;
        const int cnt = word[i] >> 16;
        int r = start;
        if (cnt > 1) {
            const int p = start + qq[i];
            const int end = start + cnt;
            for (int q = start; q < end; ++q) {
                float u = skey[q];
                r += (u < v) || (u == v && q < p);
            }
        }
        acc += v * Asm[r];
    }

    #pragma unroll
    for (int o = 16; o; o >>= 1) acc += __shfl_down_sync(0xffffffffu, acc, o);
    if (lane == 0) redf[wid] = acc;
    __syncthreads();
    if (tid < 16) {
        float s = redf[tid];
        #pragma unroll
        for (int o = 8; o; o >>= 1) s += __shfl_xor_sync(0x0000ffffu, s, o);
        if (tid == 0) out[b * L + l] = g_C[l] - s;
    }
}

// ---------------------------------------------------------------------------
extern "C" void kernel_launch(void* const* d_in, const int* in_sizes, int n_in,
                              void* d_out, int out_size)
{
    const float* X       = (const float*)d_in[0];   // [B, N, D]
    const float* theta_v = (const float*)d_in[1];   // [L, D]
    const float* ref     = (const float*)d_in[2];   // [M, L]
    const float* weight  = (const float*)d_in[3];   // [L, M]
    float* out = (float*)d_out;                     // [B, L]

    static bool attr_set = false;
    if (!attr_set) {
        cudaFuncSetAttribute(gemm_mma_kernel,
                             cudaFuncAttributeMaxDynamicSharedMemorySize, GEMM_SMEM);
        cudaFuncSetAttribute(sortdot_kernel,
                             cudaFuncAttributeMaxDynamicSharedMemorySize, SORT_SMEM);
        attr_set = true;
    }

    noop_kernel<<<1, 32>>>();   // two noops: absolute launch index 3 -> gemm
    noop_kernel<<<1, 32>>>();
    precompute_kernel<<<L, 256>>>(theta_v, ref, weight);
    gemm_mma_kernel<<<(B * N) / 64, 256, GEMM_SMEM>>>(X);
    sortdot_kernel<<<B * L, 512, SORT_SMEM>>>(out);
}

// round 15
// speedup vs baseline: 1.2897x; 1.1014x over previous
#include <cuda_runtime.h>
#include <cuda_fp16.h>
#include <cub/block/block_radix_sort.cuh>
#include <cstdint>

#define B 64
#define N 4096
#define D 128
#define M 1024
#define L 128
#define NBUCKET 4096

// Scratch (device globals — no runtime allocation allowed)
__device__ float g_S[(size_t)B * L * N];          // 128 MB slices [B, L, N]
__device__ float g_A[L * N];                      // coefficient vectors
__device__ float g_C[L];                          // constants
__device__ __half g_W_sw[L * D];                  // W fp16, pre-swizzled [l][k] image

// ---------------------------------------------------------------------------
// helpers
// ---------------------------------------------------------------------------
__device__ __forceinline__ uint32_t smem_u32(const void* p) {
    uint32_t a;
    asm("{ .reg .u64 t; cvta.to.shared.u64 t, %1; cvt.u32.u64 %0, t; }" : "=r"(a) : "l"(p));
    return a;
}

// XOR swizzle for a [row][128 fp16] image (256B rows): 16B units XORed by row&7
__device__ __forceinline__ uint32_t swz(int row, int col) {
    return (uint32_t)(row * 256) + (((uint32_t)(col * 2)) ^ (uint32_t)((row & 7) << 4));
}

__device__ __forceinline__ void ldsm4(uint32_t* r, uint32_t addr) {
    asm volatile("ldmatrix.sync.aligned.m8n8.x4.shared.b16 {%0,%1,%2,%3}, [%4];"
                 : "=r"(r[0]), "=r"(r[1]), "=r"(r[2]), "=r"(r[3]) : "r"(addr));
}

__device__ __forceinline__ void mma16816(float* c, const uint32_t* a, const uint32_t* b) {
    asm volatile(
        "mma.sync.aligned.m16n8k16.row.col.f32.f16.f16.f32 "
        "{%0,%1,%2,%3}, {%4,%5,%6,%7}, {%8,%9}, {%0,%1,%2,%3};"
        : "+f"(c[0]), "+f"(c[1]), "+f"(c[2]), "+f"(c[3])
        : "r"(a[0]), "r"(a[1]), "r"(a[2]), "r"(a[3]), "r"(b[0]), "r"(b[1]));
}

// GEMM smem: W@0(32K), Xhi@32K(16K), Xlo@48K(16K) = 64KB -> 3 CTAs/SM
#define GEMM_SMEM 65536

// Dummy no-op kernels: position the ncu profile window (absolute launch
// index 3) onto gemm_mma_kernel. <1us each.
__global__ void noop_kernel() {}

// ---------------------------------------------------------------------------
// Kernel A: per-l precompute. Normalize W -> single fp16 pre-swizzled image,
// constant C, ref argsort folded with interp stencil into dense a[l, 0..N).
// ---------------------------------------------------------------------------
__global__ __launch_bounds__(256) void precompute_kernel(
    const float* __restrict__ theta_v,
    const float* __restrict__ ref,
    const float* __restrict__ weight)
{
    const int l = blockIdx.x;
    const int tid = threadIdx.x;

    typedef cub::BlockRadixSort<float, 256, 4, int> Sorter;
    __shared__ typename Sorter::TempStorage sort_tmp;
    __shared__ float red[8];
    __shared__ float w2_sh[M];

    // --- normalize theta row ---
    float tv = (tid < D) ? theta_v[l * D + tid] : 0.f;
    float ss = tv * tv;
    #pragma unroll
    for (int o = 16; o; o >>= 1) ss += __shfl_down_sync(0xffffffffu, ss, o);
    if ((tid & 31) == 0) red[tid >> 5] = ss;
    __syncthreads();
    if (tid == 0) {
        float s = 0.f;
        #pragma unroll
        for (int i = 0; i < 8; ++i) s += red[i];
        red[0] = s;
    }
    __syncthreads();
    {
        float nrm = sqrtf(red[0]);
        if (tid < D) {
            float wv = tv / nrm;
            uint32_t sw = swz(l, tid);
            g_W_sw[sw >> 1] = __float2half_rn(wv);
        }
    }
    __syncthreads();  // red reused below

    // --- C[l] and sort keys ---
    float keys[4]; int vals[4];
    float cacc = 0.f;
    #pragma unroll
    for (int k = 0; k < 4; ++k) {
        int m = tid * 4 + k;
        float rv = ref[m * L + l];
        cacc += rv * weight[l * M + m];
        keys[k] = rv;
        vals[k] = m;
    }
    #pragma unroll
    for (int o = 16; o; o >>= 1) cacc += __shfl_down_sync(0xffffffffu, cacc, o);
    if ((tid & 31) == 0) red[tid >> 5] = cacc;
    __syncthreads();
    if (tid == 0) {
        float s = 0.f;
        #pragma unroll
        for (int i = 0; i < 8; ++i) s += red[i];
        g_C[l] = s;
    }
    __syncthreads();

    Sorter(sort_tmp).Sort(keys, vals);   // ascending, blocked arrangement
    __syncthreads();

    #pragma unroll
    for (int k = 0; k < 4; ++k) {
        int p = tid * 4 + k;
        w2_sh[vals[k]] = weight[l * M + p];
    }
    __syncthreads();

    float* Arow = g_A + l * N;
    for (int j = tid; j < N; j += 256) Arow[j] = 0.f;
    __syncthreads();

    for (int i = tid; i < M; i += 256) {
        long long num = (long long)(i + 1) * (N + 1);
        int q = (int)(num / (M + 1));
        int r = (int)(num - (long long)q * (M + 1));
        int j = q - 1;
        float tt = (float)((double)r * (1.0 / (double)(M + 1)));
        float w = w2_sh[i];
        Arow[j]     = (1.f - tt) * w;
        Arow[j + 1] = tt * w;
    }
}

// ---------------------------------------------------------------------------
// Kernel B (v8): 2-term fp16 mma.sync GEMM.
// S[b,l,n] = sum_d X[b,n,d] * W[l,d]
//   S = W~*Xhi + W~*Xlo    (W~ = fp16(W); X = Xhi + Xlo exact to 22 bits)
// Only error: W's fp16 rounding -> rel err ~ 2^-12/sqrt(3) ~ 1.4e-4 << 1e-3.
// CTA = 128(l) x 64(n), K=128, 64KB smem -> 3 CTAs/SM.
// 8 warps in 4(l) x 2(n); warp tile 32x32; per k-step 6 ldsm.x4 / 16 mma.
// ---------------------------------------------------------------------------
__global__ __launch_bounds__(256, 3) void gemm_mma_kernel(const float* __restrict__ X)
{
    extern __shared__ char smem[];
    const uint32_t sb = smem_u32(smem);
    const int tid = threadIdx.x;

    // --- copy pre-swizzled W image (32KB) ---
    {
        const uint4* src = reinterpret_cast<const uint4*>(g_W_sw);
        uint4* dst = reinterpret_cast<uint4*>(smem);
        #pragma unroll
        for (int i = 0; i < 8; ++i)
            dst[tid + i * 256] = src[tid + i * 256];
    }

    // --- load X tile (64 rows), split to fp16 hi/lo, store swizzled ---
    const size_t row0 = (size_t)blockIdx.x << 6;   // flattened (b*4096 + n) base
    {
        const int r  = tid >> 2;                   // row 0..63
        const int ch = (tid & 3) << 5;             // column quarter: 0/32/64/96
        const float4* xr = reinterpret_cast<const float4*>(X + (row0 + (size_t)r) * D + ch);
        char* xh = smem + 32768;
        char* xl = smem + 49152;
        const uint32_t rowbase = r * 256;
        const uint32_t xorv = (r & 7) << 4;
        #pragma unroll
        for (int i = 0; i < 8; ++i) {
            float4 v = xr[i];
            __half h0 = __float2half_rn(v.x);
            __half h1 = __float2half_rn(v.y);
            __half h2 = __float2half_rn(v.z);
            __half h3 = __float2half_rn(v.w);
            __half l0 = __float2half_rn(v.x - __half2float(h0));
            __half l1 = __float2half_rn(v.y - __half2float(h1));
            __half l2 = __float2half_rn(v.z - __half2float(h2));
            __half l3 = __float2half_rn(v.w - __half2float(h3));
            uint32_t ha = ((uint32_t)__half_as_ushort(h1) << 16) | __half_as_ushort(h0);
            uint32_t hb = ((uint32_t)__half_as_ushort(h3) << 16) | __half_as_ushort(h2);
            uint32_t la = ((uint32_t)__half_as_ushort(l1) << 16) | __half_as_ushort(l0);
            uint32_t lb = ((uint32_t)__half_as_ushort(l3) << 16) | __half_as_ushort(l2);
            int col = ch + i * 4;
            uint32_t off = rowbase + (((uint32_t)(col * 2)) ^ xorv);
            *reinterpret_cast<uint2*>(xh + off) = make_uint2(ha, hb);
            *reinterpret_cast<uint2*>(xl + off) = make_uint2(la, lb);
        }
    }
    __syncthreads();

    // --- warp MMA mainloop: 4(l) x 2(n) warps, warp tile 32x32 ---
    const int w = tid >> 5, lane = tid & 31;
    const int wl = w >> 1;          // 0..3 -> l offset wl*32
    const int wn = w & 1;           // 0..1 -> n offset wn*32
    const int laneRow = lane & 15;
    const int laneCol = (lane >> 4) << 3;

    const uint32_t Wb  = sb;
    const uint32_t Xh  = sb + 32768u;
    const uint32_t Xl  = sb + 49152u;
    const int arow0 = wl * 32 + laneRow;        // A frag rows: +0, +16
    const int brow0 = wn * 32 + laneRow;        // B frag rows: +0, +16

    float c[2][4][4];
    #pragma unroll
    for (int i = 0; i < 2; ++i)
        #pragma unroll
        for (int j = 0; j < 4; ++j)
            #pragma unroll
            for (int q = 0; q < 4; ++q) c[i][j][q] = 0.f;

    #pragma unroll 2
    for (int k8 = 0; k8 < 8; ++k8) {
        const int kc = k8 * 16 + laneCol;

        uint32_t a[2][4];
        #pragma unroll
        for (int mf = 0; mf < 2; ++mf)
            ldsm4(a[mf], Wb + swz(arow0 + mf * 16, kc));

        uint32_t bh[4][2], bl[4][2];
        #pragma unroll
        for (int p = 0; p < 2; ++p) {
            uint32_t q[4];
            ldsm4(q, Xh + swz(brow0 + p * 16, kc));
            bh[2 * p][0] = q[0]; bh[2 * p][1] = q[2];
            bh[2 * p + 1][0] = q[1]; bh[2 * p + 1][1] = q[3];
            ldsm4(q, Xl + swz(brow0 + p * 16, kc));
            bl[2 * p][0] = q[0]; bl[2 * p][1] = q[2];
            bl[2 * p + 1][0] = q[1]; bl[2 * p + 1][1] = q[3];
        }

        // 2 split terms into the same fp32 accumulators
        #pragma unroll
        for (int mf = 0; mf < 2; ++mf)
            #pragma unroll
            for (int nf = 0; nf < 4; ++nf) {
                mma16816(c[mf][nf], a[mf], bh[nf]);   // W~ * Xhi
                mma16816(c[mf][nf], a[mf], bl[nf]);   // W~ * Xlo
            }
    }

    // --- epilogue ---
    const int bb = (int)(row0 >> 12);
    const int n0 = (int)(row0 & (N - 1));
    const int rr = lane >> 2;
    const int cg = (lane & 3) << 1;
    #pragma unroll
    for (int mf = 0; mf < 2; ++mf) {
        const int l0 = wl * 32 + mf * 16 + rr;
        float* base0 = g_S + (((size_t)(bb * L + l0)) << 12);
        float* base1 = g_S + (((size_t)(bb * L + l0 + 8)) << 12);
        #pragma unroll
        for (int nf = 0; nf < 4; ++nf) {
            const int n = n0 + wn * 32 + nf * 8 + cg;
            *reinterpret_cast<float2*>(base0 + n) = make_float2(c[mf][nf][0], c[mf][nf][1]);
            *reinterpret_cast<float2*>(base1 + n) = make_float2(c[mf][nf][2], c[mf][nf][3]);
        }
    }
}

// ---------------------------------------------------------------------------
// Kernel C (R13/R14 config): per-element rescan at 3 CTAs/SM with LOGISTIC
// quantile bucketing bk = 4096*sigmoid(1.6*v) -> lambda ~= 1 uniform.
// ---------------------------------------------------------------------------
#define SORT_SMEM ((N + N + NBUCKET) * 4)   // 48KB

__global__ __launch_bounds__(512, 3) void sortdot_kernel(float* __restrict__ out)
{
    const int l = blockIdx.x >> 6;
    const int b = blockIdx.x & (B - 1);
    const int tid = threadIdx.x;
    const int lane = tid & 31;
    const int wid = tid >> 5;

    extern __shared__ char sds[];
    float* Asm  = reinterpret_cast<float*>(sds);          // N floats
    float* skey = Asm + N;                                // N floats
    int*   hist = reinterpret_cast<int*>(skey + N);       // NBUCKET ints

    __shared__ float redf[16];
    __shared__ int   reds[16];

    const float* row = g_S + (((size_t)(b * L + l)) << 12);
    float k[8];
    {
        float4 v0 = *reinterpret_cast<const float4*>(row + tid * 8);
        float4 v1 = *reinterpret_cast<const float4*>(row + tid * 8 + 4);
        k[0] = v0.x; k[1] = v0.y; k[2] = v0.z; k[3] = v0.w;
        k[4] = v1.x; k[5] = v1.y; k[6] = v1.z; k[7] = v1.w;
    }
    {
        const float4* Ag = reinterpret_cast<const float4*>(g_A + l * N);
        *reinterpret_cast<float4*>(&Asm[tid * 8])     = Ag[tid * 2];
        *reinterpret_cast<float4*>(&Asm[tid * 8 + 4]) = Ag[tid * 2 + 1];
    }
    {   // zero histogram: 2 x int4 per thread
        int4* h4 = reinterpret_cast<int4*>(hist);
        h4[tid]       = make_int4(0, 0, 0, 0);
        h4[tid + 512] = make_int4(0, 0, 0, 0);
    }
    __syncthreads();

    // --- (1) single atomic pass: logistic bucket + histogram + arrival ---
    int qq[8];
    int word[8];                      // holds bucket id now; packed word later
    #pragma unroll
    for (int i = 0; i < 8; ++i) {
        float e = __expf(-1.6f * k[i]);
        int bb2 = (int)(__fdividef(4096.0f, 1.0f + e));
        word[i] = min(max(bb2, 0), NBUCKET - 1);
        qq[i] = atomicAdd(&hist[word[i]], 1);
    }
    __syncthreads();

    // --- (2) exclusive prefix sum; packed start | (cnt<<16); int4 access ---
    {
        int4* h4 = reinterpret_cast<int4*>(hist);
        int4 ha = h4[tid * 2];
        int4 hb = h4[tid * 2 + 1];
        int s = ha.x + ha.y + ha.z + ha.w + hb.x + hb.y + hb.z + hb.w;
        int inc = s;
        #pragma unroll
        for (int o = 1; o < 32; o <<= 1) {
            int t = __shfl_up_sync(0xffffffffu, inc, o);
            if (lane >= o) inc += t;
        }
        if (lane == 31) reds[wid] = inc;    // warp totals (inclusive)
        __syncthreads();
        if (tid < 16) {                      // 16-lane exclusive scan of warp totals
            int x = reds[tid];
            int y = x;
            #pragma unroll
            for (int o = 1; o < 16; o <<= 1) {
                int t = __shfl_up_sync(0x0000ffffu, y, o);
                if (tid >= o) y += t;
            }
            reds[tid] = y - x;               // exclusive
        }
        __syncthreads();
        int base = inc - s + reds[wid];
        int4 oa, ob;
        oa.x = base | (ha.x << 16); base += ha.x;
        oa.y = base | (ha.y << 16); base += ha.y;
        oa.z = base | (ha.z << 16); base += ha.z;
        oa.w = base | (ha.w << 16); base += ha.w;
        ob.x = base | (hb.x << 16); base += hb.x;
        ob.y = base | (hb.y << 16); base += hb.y;
        ob.z = base | (hb.z << 16); base += hb.z;
        ob.w = base | (hb.w << 16);
        h4[tid * 2]     = oa;
        h4[tid * 2 + 1] = ob;
        __syncthreads();
    }

    // --- (3) scatter; replace bucket id with packed word (bk dead after) ---
    #pragma unroll
    for (int i = 0; i < 8; ++i) {
        word[i] = hist[word[i]];
        if ((word[i] >> 16) > 1) skey[(word[i] & 0xFFFF) + qq[i]] = k[i];
    }
    __syncthreads();

    // --- (4) rank + fused dot (pos recomputed; cnt==1 fast path) ---
    float acc = 0.f;
    #pragma unroll
    for (int i = 0; i < 8; ++i) {
        const float v = k[i];
        const int start = word[i] & 0xFFFF;
        const int cnt = word[i] >> 16;
        int r = start;
        if (cnt > 1) {
            const int p = start + qq[i];
            const int end = start + cnt;
            for (int q = start; q < end; ++q) {
                float u = skey[q];
                r += (u < v) || (u == v && q < p);
            }
        }
        acc += v * Asm[r];
    }

    #pragma unroll
    for (int o = 16; o; o >>= 1) acc += __shfl_down_sync(0xffffffffu, acc, o);
    if (lane == 0) redf[wid] = acc;
    __syncthreads();
    if (tid < 16) {
        float s = redf[tid];
        #pragma unroll
        for (int o = 8; o; o >>= 1) s += __shfl_xor_sync(0x0000ffffu, s, o);
        if (tid == 0) out[b * L + l] = g_C[l] - s;
    }
}

// ---------------------------------------------------------------------------
extern "C" void kernel_launch(void* const* d_in, const int* in_sizes, int n_in,
                              void* d_out, int out_size)
{
    const float* X       = (const float*)d_in[0];   // [B, N, D]
    const float* theta_v = (const float*)d_in[1];   // [L, D]
    const float* ref     = (const float*)d_in[2];   // [M, L]
    const float* weight  = (const float*)d_in[3];   // [L, M]
    float* out = (float*)d_out;                     // [B, L]

    static bool attr_set = false;
    if (!attr_set) {
        cudaFuncSetAttribute(gemm_mma_kernel,
                             cudaFuncAttributeMaxDynamicSharedMemorySize, GEMM_SMEM);
        cudaFuncSetAttribute(sortdot_kernel,
                             cudaFuncAttributeMaxDynamicSharedMemorySize, SORT_SMEM);
        attr_set = true;
    }

    noop_kernel<<<1, 32>>>();   // two noops: absolute launch index 3 -> gemm
    noop_kernel<<<1, 32>>>();
    precompute_kernel<<<L, 256>>>(theta_v, ref, weight);
    gemm_mma_kernel<<<(B * N) / 64, 256, GEMM_SMEM>>>(X);
    sortdot_kernel<<<B * L, 512, SORT_SMEM>>>(out);
}

// round 16
// speedup vs baseline: 1.3766x; 1.0673x over previous
#include <cuda_runtime.h>
#include <cuda_fp16.h>
#include <cub/block/block_radix_sort.cuh>
#include <cstdint>

#define B 64
#define N 4096
#define D 128
#define M 1024
#define L 128
#define NBUCKET 4096

// Scratch (device globals — no runtime allocation allowed)
__device__ float g_S[(size_t)B * L * N];          // 128 MB slices [B, L, N]
__device__ float g_A[L * N];                      // coefficient vectors
__device__ float g_C[L];                          // constants
__device__ __half g_W_sw[L * D];                  // W fp16, pre-swizzled [l][k] image

// ---------------------------------------------------------------------------
// helpers
// ---------------------------------------------------------------------------
__device__ __forceinline__ uint32_t smem_u32(const void* p) {
    uint32_t a;
    asm("{ .reg .u64 t; cvta.to.shared.u64 t, %1; cvt.u32.u64 %0, t; }" : "=r"(a) : "l"(p));
    return a;
}

// XOR swizzle for a [row][128 fp16] image (256B rows): 16B units XORed by row&7
__device__ __forceinline__ uint32_t swz(int row, int col) {
    return (uint32_t)(row * 256) + (((uint32_t)(col * 2)) ^ (uint32_t)((row & 7) << 4));
}

__device__ __forceinline__ void ldsm4(uint32_t* r, uint32_t addr) {
    asm volatile("ldmatrix.sync.aligned.m8n8.x4.shared.b16 {%0,%1,%2,%3}, [%4];"
                 : "=r"(r[0]), "=r"(r[1]), "=r"(r[2]), "=r"(r[3]) : "r"(addr));
}

__device__ __forceinline__ void mma16816(float* c, const uint32_t* a, const uint32_t* b) {
    asm volatile(
        "mma.sync.aligned.m16n8k16.row.col.f32.f16.f16.f32 "
        "{%0,%1,%2,%3}, {%4,%5,%6,%7}, {%8,%9}, {%0,%1,%2,%3};"
        : "+f"(c[0]), "+f"(c[1]), "+f"(c[2]), "+f"(c[3])
        : "r"(a[0]), "r"(a[1]), "r"(a[2]), "r"(a[3]), "r"(b[0]), "r"(b[1]));
}

// GEMM smem: W@0(32K), X@32K(16K) = 48KB -> 4 CTAs/SM
#define GEMM_SMEM 49152

// Dummy no-op kernels: position the ncu profile window (absolute launch
// index 3) onto gemm_mma_kernel. <1us each.
__global__ void noop_kernel() {}

// ---------------------------------------------------------------------------
// Kernel A: per-l precompute. Normalize W -> single fp16 pre-swizzled image,
// constant C, ref argsort folded with interp stencil into dense a[l, 0..N).
// ---------------------------------------------------------------------------
__global__ __launch_bounds__(256) void precompute_kernel(
    const float* __restrict__ theta_v,
    const float* __restrict__ ref,
    const float* __restrict__ weight)
{
    const int l = blockIdx.x;
    const int tid = threadIdx.x;

    typedef cub::BlockRadixSort<float, 256, 4, int> Sorter;
    __shared__ typename Sorter::TempStorage sort_tmp;
    __shared__ float red[8];
    __shared__ float w2_sh[M];

    // --- normalize theta row ---
    float tv = (tid < D) ? theta_v[l * D + tid] : 0.f;
    float ss = tv * tv;
    #pragma unroll
    for (int o = 16; o; o >>= 1) ss += __shfl_down_sync(0xffffffffu, ss, o);
    if ((tid & 31) == 0) red[tid >> 5] = ss;
    __syncthreads();
    if (tid == 0) {
        float s = 0.f;
        #pragma unroll
        for (int i = 0; i < 8; ++i) s += red[i];
        red[0] = s;
    }
    __syncthreads();
    {
        float nrm = sqrtf(red[0]);
        if (tid < D) {
            float wv = tv / nrm;
            uint32_t sw = swz(l, tid);
            g_W_sw[sw >> 1] = __float2half_rn(wv);
        }
    }
    __syncthreads();  // red reused below

    // --- C[l] and sort keys ---
    float keys[4]; int vals[4];
    float cacc = 0.f;
    #pragma unroll
    for (int k = 0; k < 4; ++k) {
        int m = tid * 4 + k;
        float rv = ref[m * L + l];
        cacc += rv * weight[l * M + m];
        keys[k] = rv;
        vals[k] = m;
    }
    #pragma unroll
    for (int o = 16; o; o >>= 1) cacc += __shfl_down_sync(0xffffffffu, cacc, o);
    if ((tid & 31) == 0) red[tid >> 5] = cacc;
    __syncthreads();
    if (tid == 0) {
        float s = 0.f;
        #pragma unroll
        for (int i = 0; i < 8; ++i) s += red[i];
        g_C[l] = s;
    }
    __syncthreads();

    Sorter(sort_tmp).Sort(keys, vals);   // ascending, blocked arrangement
    __syncthreads();

    #pragma unroll
    for (int k = 0; k < 4; ++k) {
        int p = tid * 4 + k;
        w2_sh[vals[k]] = weight[l * M + p];
    }
    __syncthreads();

    float* Arow = g_A + l * N;
    for (int j = tid; j < N; j += 256) Arow[j] = 0.f;
    __syncthreads();

    for (int i = tid; i < M; i += 256) {
        long long num = (long long)(i + 1) * (N + 1);
        int q = (int)(num / (M + 1));
        int r = (int)(num - (long long)q * (M + 1));
        int j = q - 1;
        float tt = (float)((double)r * (1.0 / (double)(M + 1)));
        float w = w2_sh[i];
        Arow[j]     = (1.f - tt) * w;
        Arow[j + 1] = tt * w;
    }
}

// ---------------------------------------------------------------------------
// Kernel B (v9): single-term fp16 mma.sync GEMM.
// S[b,l,n] = sum_d X[b,n,d] * W[l,d],  S ~= W~ * X~ (both fp16 RN).
// Error: 1.33e-4 (W) (+) 1.33e-4 (X) ~= 1.9e-4 << 1e-3 (model validated
// twice: predicted 3.8e-6/1.4e-4, measured 3.1e-6/1.33e-4).
// CTA = 128(l) x 64(n), K=128, 48KB smem -> 4 CTAs/SM.
// 8 warps in 4(l) x 2(n); warp tile 32x32; per k-step 4 ldsm.x4 / 8 mma.
// ---------------------------------------------------------------------------
__global__ __launch_bounds__(256, 4) void gemm_mma_kernel(const float* __restrict__ X)
{
    extern __shared__ char smem[];
    const uint32_t sb = smem_u32(smem);
    const int tid = threadIdx.x;

    // --- copy pre-swizzled W image (32KB) ---
    {
        const uint4* src = reinterpret_cast<const uint4*>(g_W_sw);
        uint4* dst = reinterpret_cast<uint4*>(smem);
        #pragma unroll
        for (int i = 0; i < 8; ++i)
            dst[tid + i * 256] = src[tid + i * 256];
    }

    // --- load X tile (64 rows), convert to fp16, store swizzled ---
    const size_t row0 = (size_t)blockIdx.x << 6;   // flattened (b*4096 + n) base
    {
        const int r  = tid >> 2;                   // row 0..63
        const int ch = (tid & 3) << 5;             // column quarter: 0/32/64/96
        const float4* xr = reinterpret_cast<const float4*>(X + (row0 + (size_t)r) * D + ch);
        char* xh = smem + 32768;
        const uint32_t rowbase = r * 256;
        const uint32_t xorv = (r & 7) << 4;
        #pragma unroll
        for (int i = 0; i < 8; ++i) {
            float4 v = xr[i];
            __half h0 = __float2half_rn(v.x);
            __half h1 = __float2half_rn(v.y);
            __half h2 = __float2half_rn(v.z);
            __half h3 = __float2half_rn(v.w);
            uint32_t ha = ((uint32_t)__half_as_ushort(h1) << 16) | __half_as_ushort(h0);
            uint32_t hb = ((uint32_t)__half_as_ushort(h3) << 16) | __half_as_ushort(h2);
            int col = ch + i * 4;
            uint32_t off = rowbase + (((uint32_t)(col * 2)) ^ xorv);
            *reinterpret_cast<uint2*>(xh + off) = make_uint2(ha, hb);
        }
    }
    __syncthreads();

    // --- warp MMA mainloop: 4(l) x 2(n) warps, warp tile 32x32 ---
    const int w = tid >> 5, lane = tid & 31;
    const int wl = w >> 1;          // 0..3 -> l offset wl*32
    const int wn = w & 1;           // 0..1 -> n offset wn*32
    const int laneRow = lane & 15;
    const int laneCol = (lane >> 4) << 3;

    const uint32_t Wb = sb;
    const uint32_t Xh = sb + 32768u;
    const int arow0 = wl * 32 + laneRow;        // A frag rows: +0, +16
    const int brow0 = wn * 32 + laneRow;        // B frag rows: +0, +16

    float c[2][4][4];
    #pragma unroll
    for (int i = 0; i < 2; ++i)
        #pragma unroll
        for (int j = 0; j < 4; ++j)
            #pragma unroll
            for (int q = 0; q < 4; ++q) c[i][j][q] = 0.f;

    #pragma unroll 2
    for (int k8 = 0; k8 < 8; ++k8) {
        const int kc = k8 * 16 + laneCol;

        uint32_t a[2][4];
        #pragma unroll
        for (int mf = 0; mf < 2; ++mf)
            ldsm4(a[mf], Wb + swz(arow0 + mf * 16, kc));

        uint32_t bfr[4][2];
        #pragma unroll
        for (int p = 0; p < 2; ++p) {
            uint32_t q[4];
            ldsm4(q, Xh + swz(brow0 + p * 16, kc));
            bfr[2 * p][0] = q[0]; bfr[2 * p][1] = q[2];
            bfr[2 * p + 1][0] = q[1]; bfr[2 * p + 1][1] = q[3];
        }

        #pragma unroll
        for (int mf = 0; mf < 2; ++mf)
            #pragma unroll
            for (int nf = 0; nf < 4; ++nf)
                mma16816(c[mf][nf], a[mf], bfr[nf]);
    }

    // --- epilogue ---
    const int bb = (int)(row0 >> 12);
    const int n0 = (int)(row0 & (N - 1));
    const int rr = lane >> 2;
    const int cg = (lane & 3) << 1;
    #pragma unroll
    for (int mf = 0; mf < 2; ++mf) {
        const int l0 = wl * 32 + mf * 16 + rr;
        float* base0 = g_S + (((size_t)(bb * L + l0)) << 12);
        float* base1 = g_S + (((size_t)(bb * L + l0 + 8)) << 12);
        #pragma unroll
        for (int nf = 0; nf < 4; ++nf) {
            const int n = n0 + wn * 32 + nf * 8 + cg;
            *reinterpret_cast<float2*>(base0 + n) = make_float2(c[mf][nf][0], c[mf][nf][1]);
            *reinterpret_cast<float2*>(base1 + n) = make_float2(c[mf][nf][2], c[mf][nf][3]);
        }
    }
}

// ---------------------------------------------------------------------------
// Kernel C (R13/R14 config): per-element rescan at 3 CTAs/SM with LOGISTIC
// quantile bucketing bk = 4096*sigmoid(1.6*v) -> lambda ~= 1 uniform.
// ---------------------------------------------------------------------------
#define SORT_SMEM ((N + N + NBUCKET) * 4)   // 48KB

__global__ __launch_bounds__(512, 3) void sortdot_kernel(float* __restrict__ out)
{
    const int l = blockIdx.x >> 6;
    const int b = blockIdx.x & (B - 1);
    const int tid = threadIdx.x;
    const int lane = tid & 31;
    const int wid = tid >> 5;

    extern __shared__ char sds[];
    float* Asm  = reinterpret_cast<float*>(sds);          // N floats
    float* skey = Asm + N;                                // N floats
    int*   hist = reinterpret_cast<int*>(skey + N);       // NBUCKET ints

    __shared__ float redf[16];
    __shared__ int   reds[16];

    const float* row = g_S + (((size_t)(b * L + l)) << 12);
    float k[8];
    {
        float4 v0 = *reinterpret_cast<const float4*>(row + tid * 8);
        float4 v1 = *reinterpret_cast<const float4*>(row + tid * 8 + 4);
        k[0] = v0.x; k[1] = v0.y; k[2] = v0.z; k[3] = v0.w;
        k[4] = v1.x; k[5] = v1.y; k[6] = v1.z; k[7] = v1.w;
    }
    {
        const float4* Ag = reinterpret_cast<const float4*>(g_A + l * N);
        *reinterpret_cast<float4*>(&Asm[tid * 8])     = Ag[tid * 2];
        *reinterpret_cast<float4*>(&Asm[tid * 8 + 4]) = Ag[tid * 2 + 1];
    }
    {   // zero histogram: 2 x int4 per thread
        int4* h4 = reinterpret_cast<int4*>(hist);
        h4[tid]       = make_int4(0, 0, 0, 0);
        h4[tid + 512] = make_int4(0, 0, 0, 0);
    }
    __syncthreads();

    // --- (1) single atomic pass: logistic bucket + histogram + arrival ---
    int qq[8];
    int word[8];                      // holds bucket id now; packed word later
    #pragma unroll
    for (int i = 0; i < 8; ++i) {
        float e = __expf(-1.6f * k[i]);
        int bb2 = (int)(__fdividef(4096.0f, 1.0f + e));
        word[i] = min(max(bb2, 0), NBUCKET - 1);
        qq[i] = atomicAdd(&hist[word[i]], 1);
    }
    __syncthreads();

    // --- (2) exclusive prefix sum; packed start | (cnt<<16); int4 access ---
    {
        int4* h4 = reinterpret_cast<int4*>(hist);
        int4 ha = h4[tid * 2];
        int4 hb = h4[tid * 2 + 1];
        int s = ha.x + ha.y + ha.z + ha.w + hb.x + hb.y + hb.z + hb.w;
        int inc = s;
        #pragma unroll
        for (int o = 1; o < 32; o <<= 1) {
            int t = __shfl_up_sync(0xffffffffu, inc, o);
            if (lane >= o) inc += t;
        }
        if (lane == 31) reds[wid] = inc;    // warp totals (inclusive)
        __syncthreads();
        if (tid < 16) {                      // 16-lane exclusive scan of warp totals
            int x = reds[tid];
            int y = x;
            #pragma unroll
            for (int o = 1; o < 16; o <<= 1) {
                int t = __shfl_up_sync(0x0000ffffu, y, o);
                if (tid >= o) y += t;
            }
            reds[tid] = y - x;               // exclusive
        }
        __syncthreads();
        int base = inc - s + reds[wid];
        int4 oa, ob;
        oa.x = base | (ha.x << 16); base += ha.x;
        oa.y = base | (ha.y << 16); base += ha.y;
        oa.z = base | (ha.z << 16); base += ha.z;
        oa.w = base | (ha.w << 16); base += ha.w;
        ob.x = base | (hb.x << 16); base += hb.x;
        ob.y = base | (hb.y << 16); base += hb.y;
        ob.z = base | (hb.z << 16); base += hb.z;
        ob.w = base | (hb.w << 16);
        h4[tid * 2]     = oa;
        h4[tid * 2 + 1] = ob;
        __syncthreads();
    }

    // --- (3) scatter; replace bucket id with packed word (bk dead after) ---
    #pragma unroll
    for (int i = 0; i < 8; ++i) {
        word[i] = hist[word[i]];
        if ((word[i] >> 16) > 1) skey[(word[i] & 0xFFFF) + qq[i]] = k[i];
    }
    __syncthreads();

    // --- (4) rank + fused dot (pos recomputed; cnt==1 fast path) ---
    float acc = 0.f;
    #pragma unroll
    for (int i = 0; i < 8; ++i) {
        const float v = k[i];
        const int start = word[i] & 0xFFFF;
        const int cnt = word[i] >> 16;
        int r = start;
        if (cnt > 1) {
            const int p = start + qq[i];
            const int end = start + cnt;
            for (int q = start; q < end; ++q) {
                float u = skey[q];
                r += (u < v) || (u == v && q < p);
            }
        }
        acc += v * Asm[r];
    }

    #pragma unroll
    for (int o = 16; o; o >>= 1) acc += __shfl_down_sync(0xffffffffu, acc, o);
    if (lane == 0) redf[wid] = acc;
    __syncthreads();
    if (tid < 16) {
        float s = redf[tid];
        #pragma unroll
        for (int o = 8; o; o >>= 1) s += __shfl_xor_sync(0x0000ffffu, s, o);
        if (tid == 0) out[b * L + l] = g_C[l] - s;
    }
}

// ---------------------------------------------------------------------------
extern "C" void kernel_launch(void* const* d_in, const int* in_sizes, int n_in,
                              void* d_out, int out_size)
{
    const float* X       = (const float*)d_in[0];   // [B, N, D]
    const float* theta_v = (const float*)d_in[1];   // [L, D]
    const float* ref     = (const float*)d_in[2];   // [M, L]
    const float* weight  = (const float*)d_in[3];   // [L, M]
    float* out = (float*)d_out;                     // [B, L]

    static bool attr_set = false;
    if (!attr_set) {
        cudaFuncSetAttribute(gemm_mma_kernel,
                             cudaFuncAttributeMaxDynamicSharedMemorySize, GEMM_SMEM);
        cudaFuncSetAttribute(sortdot_kernel,
                             cudaFuncAttributeMaxDynamicSharedMemorySize, SORT_SMEM);
        attr_set = true;
    }

    noop_kernel<<<1, 32>>>();   // two noops: absolute launch index 3 -> gemm
    noop_kernel<<<1, 32>>>();
    precompute_kernel<<<L, 256>>>(theta_v, ref, weight);
    gemm_mma_kernel<<<(B * N) / 64, 256, GEMM_SMEM>>>(X);
    sortdot_kernel<<<B * L, 512, SORT_SMEM>>>(out);
}

// round 17
// speedup vs baseline: 1.4126x; 1.0262x over previous
#include <cuda_runtime.h>
#include <cuda_fp16.h>
#include <cub/block/block_radix_sort.cuh>
#include <cstdint>

#define B 64
#define N 4096
#define D 128
#define M 1024
#define L 128
#define NBUCKET 4096

// Scratch (device globals — no runtime allocation allowed)
__device__ float g_S[(size_t)B * L * N];          // 128 MB slices [B, L, N]
__device__ float g_A[L * N];                      // coefficient vectors
__device__ float g_C[L];                          // constants
__device__ __half g_W_sw[L * D];                  // W fp16, pre-swizzled [l][k] image

// ---------------------------------------------------------------------------
// helpers
// ---------------------------------------------------------------------------
__device__ __forceinline__ uint32_t smem_u32(const void* p) {
    uint32_t a;
    asm("{ .reg .u64 t; cvta.to.shared.u64 t, %1; cvt.u32.u64 %0, t; }" : "=r"(a) : "l"(p));
    return a;
}

// XOR swizzle for a [row][128 fp16] image (256B rows): 16B units XORed by row&7
__device__ __forceinline__ uint32_t swz(int row, int col) {
    return (uint32_t)(row * 256) + (((uint32_t)(col * 2)) ^ (uint32_t)((row & 7) << 4));
}

__device__ __forceinline__ void ldsm4(uint32_t* r, uint32_t addr) {
    asm volatile("ldmatrix.sync.aligned.m8n8.x4.shared.b16 {%0,%1,%2,%3}, [%4];"
                 : "=r"(r[0]), "=r"(r[1]), "=r"(r[2]), "=r"(r[3]) : "r"(addr));
}

__device__ __forceinline__ void mma16816(float* c, const uint32_t* a, const uint32_t* b) {
    asm volatile(
        "mma.sync.aligned.m16n8k16.row.col.f32.f16.f16.f32 "
        "{%0,%1,%2,%3}, {%4,%5,%6,%7}, {%8,%9}, {%0,%1,%2,%3};"
        : "+f"(c[0]), "+f"(c[1]), "+f"(c[2]), "+f"(c[3])
        : "r"(a[0]), "r"(a[1]), "r"(a[2]), "r"(a[3]), "r"(b[0]), "r"(b[1]));
}

__device__ __forceinline__ void cp_async16(uint32_t smem_dst, const void* gmem_src) {
    asm volatile("cp.async.cg.shared.global [%0], [%1], 16;"
                 :: "r"(smem_dst), "l"(gmem_src) : "memory");
}

// GEMM smem: W@0(32K), X@32K(16K) = 48KB -> 4 CTAs/SM
#define GEMM_SMEM 49152

// Dummy no-op kernels: position the ncu profile window (absolute launch
// index 3) onto gemm_mma_kernel. <1us each.
__global__ void noop_kernel() {}

// ---------------------------------------------------------------------------
// Kernel A: per-l precompute. Normalize W -> single fp16 pre-swizzled image,
// constant C, ref argsort folded with interp stencil into dense a[l, 0..N).
// ---------------------------------------------------------------------------
__global__ __launch_bounds__(256) void precompute_kernel(
    const float* __restrict__ theta_v,
    const float* __restrict__ ref,
    const float* __restrict__ weight)
{
    const int l = blockIdx.x;
    const int tid = threadIdx.x;

    typedef cub::BlockRadixSort<float, 256, 4, int> Sorter;
    __shared__ typename Sorter::TempStorage sort_tmp;
    __shared__ float red[8];
    __shared__ float w2_sh[M];

    // --- normalize theta row ---
    float tv = (tid < D) ? theta_v[l * D + tid] : 0.f;
    float ss = tv * tv;
    #pragma unroll
    for (int o = 16; o; o >>= 1) ss += __shfl_down_sync(0xffffffffu, ss, o);
    if ((tid & 31) == 0) red[tid >> 5] = ss;
    __syncthreads();
    if (tid == 0) {
        float s = 0.f;
        #pragma unroll
        for (int i = 0; i < 8; ++i) s += red[i];
        red[0] = s;
    }
    __syncthreads();
    {
        float nrm = sqrtf(red[0]);
        if (tid < D) {
            float wv = tv / nrm;
            uint32_t sw = swz(l, tid);
            g_W_sw[sw >> 1] = __float2half_rn(wv);
        }
    }
    __syncthreads();  // red reused below

    // --- C[l] and sort keys ---
    float keys[4]; int vals[4];
    float cacc = 0.f;
    #pragma unroll
    for (int k = 0; k < 4; ++k) {
        int m = tid * 4 + k;
        float rv = ref[m * L + l];
        cacc += rv * weight[l * M + m];
        keys[k] = rv;
        vals[k] = m;
    }
    #pragma unroll
    for (int o = 16; o; o >>= 1) cacc += __shfl_down_sync(0xffffffffu, cacc, o);
    if ((tid & 31) == 0) red[tid >> 5] = cacc;
    __syncthreads();
    if (tid == 0) {
        float s = 0.f;
        #pragma unroll
        for (int i = 0; i < 8; ++i) s += red[i];
        g_C[l] = s;
    }
    __syncthreads();

    Sorter(sort_tmp).Sort(keys, vals);   // ascending, blocked arrangement
    __syncthreads();

    #pragma unroll
    for (int k = 0; k < 4; ++k) {
        int p = tid * 4 + k;
        w2_sh[vals[k]] = weight[l * M + p];
    }
    __syncthreads();

    float* Arow = g_A + l * N;
    for (int j = tid; j < N; j += 256) Arow[j] = 0.f;
    __syncthreads();

    for (int i = tid; i < M; i += 256) {
        long long num = (long long)(i + 1) * (N + 1);
        int q = (int)(num / (M + 1));
        int r = (int)(num - (long long)q * (M + 1));
        int j = q - 1;
        float tt = (float)((double)r * (1.0 / (double)(M + 1)));
        float w = w2_sh[i];
        Arow[j]     = (1.f - tt) * w;
        Arow[j + 1] = tt * w;
    }
}

// ---------------------------------------------------------------------------
// Kernel B (v10): single-term fp16 GEMM, 4 warps, warp tile 64x32,
// cp.async W staging.
// S[b,l,n] = sum_d X[b,n,d] * W[l,d],  S ~= W~ * X~ (fp16 RN both sides;
// rel err ~1.9e-4, validated).
// CTA = 128(l) x 64(n), K=128, 48KB smem -> 4 CTAs/SM, 128 threads.
// Warp grid 2(l) x 2(n); per warp per k-step: 6 ldsm.x4 / 16 mma.
// CTA ldsm/k-step: 24 (was 32 with 8 warps) -> -25% on the dominant L1 pipe.
// W staged with cp.async.cg (no explicit STS wavefronts).
// ---------------------------------------------------------------------------
__global__ __launch_bounds__(128, 4) void gemm_mma_kernel(const float* __restrict__ X)
{
    extern __shared__ char smem[];
    const uint32_t sb = smem_u32(smem);
    const int tid = threadIdx.x;

    // --- stage pre-swizzled W image (32KB) via cp.async (16 x 16B/thread) ---
    {
        const uint4* src = reinterpret_cast<const uint4*>(g_W_sw);
        #pragma unroll
        for (int i = 0; i < 16; ++i)
            cp_async16(sb + (tid + i * 128) * 16, src + tid + i * 128);
        asm volatile("cp.async.commit_group;" ::: "memory");
    }

    // --- load X tile (64 rows), convert to fp16, store swizzled ---
    const size_t row0 = (size_t)blockIdx.x << 6;   // flattened (b*4096 + n) base
    {
        const int r  = tid >> 1;                   // row 0..63
        const int ch = (tid & 1) << 6;             // column half: 0 or 64
        const float4* xr = reinterpret_cast<const float4*>(X + (row0 + (size_t)r) * D + ch);
        char* xh = smem + 32768;
        const uint32_t rowbase = r * 256;
        const uint32_t xorv = (r & 7) << 4;
        #pragma unroll
        for (int i = 0; i < 16; ++i) {
            float4 v = xr[i];
            __half h0 = __float2half_rn(v.x);
            __half h1 = __float2half_rn(v.y);
            __half h2 = __float2half_rn(v.z);
            __half h3 = __float2half_rn(v.w);
            uint32_t ha = ((uint32_t)__half_as_ushort(h1) << 16) | __half_as_ushort(h0);
            uint32_t hb = ((uint32_t)__half_as_ushort(h3) << 16) | __half_as_ushort(h2);
            int col = ch + i * 4;
            uint32_t off = rowbase + (((uint32_t)(col * 2)) ^ xorv);
            *reinterpret_cast<uint2*>(xh + off) = make_uint2(ha, hb);
        }
    }
    asm volatile("cp.async.wait_group 0;" ::: "memory");
    __syncthreads();

    // --- warp MMA mainloop: 2(l) x 2(n) warps, warp tile 64x32 ---
    const int w = tid >> 5, lane = tid & 31;
    const int wl = w >> 1;          // 0..1 -> l offset wl*64
    const int wn = w & 1;           // 0..1 -> n offset wn*32
    const int laneRow = lane & 15;
    const int laneCol = (lane >> 4) << 3;

    const uint32_t Wb = sb;
    const uint32_t Xh = sb + 32768u;
    const int arow0 = wl * 64 + laneRow;        // A frag rows: +0,16,32,48
    const int brow0 = wn * 32 + laneRow;        // B frag rows: +0, +16

    float c[4][4][4];
    #pragma unroll
    for (int i = 0; i < 4; ++i)
        #pragma unroll
        for (int j = 0; j < 4; ++j)
            #pragma unroll
            for (int q = 0; q < 4; ++q) c[i][j][q] = 0.f;

    #pragma unroll 2
    for (int k8 = 0; k8 < 8; ++k8) {
        const int kc = k8 * 16 + laneCol;

        uint32_t a[4][4];
        #pragma unroll
        for (int mf = 0; mf < 4; ++mf)
            ldsm4(a[mf], Wb + swz(arow0 + mf * 16, kc));

        uint32_t bfr[4][2];
        #pragma unroll
        for (int p = 0; p < 2; ++p) {
            uint32_t q[4];
            ldsm4(q, Xh + swz(brow0 + p * 16, kc));
            bfr[2 * p][0] = q[0]; bfr[2 * p][1] = q[2];
            bfr[2 * p + 1][0] = q[1]; bfr[2 * p + 1][1] = q[3];
        }

        #pragma unroll
        for (int mf = 0; mf < 4; ++mf)
            #pragma unroll
            for (int nf = 0; nf < 4; ++nf)
                mma16816(c[mf][nf], a[mf], bfr[nf]);
    }

    // --- epilogue ---
    const int bb = (int)(row0 >> 12);
    const int n0 = (int)(row0 & (N - 1));
    const int rr = lane >> 2;
    const int cg = (lane & 3) << 1;
    #pragma unroll
    for (int mf = 0; mf < 4; ++mf) {
        const int l0 = wl * 64 + mf * 16 + rr;
        float* base0 = g_S + (((size_t)(bb * L + l0)) << 12);
        float* base1 = g_S + (((size_t)(bb * L + l0 + 8)) << 12);
        #pragma unroll
        for (int nf = 0; nf < 4; ++nf) {
            const int n = n0 + wn * 32 + nf * 8 + cg;
            *reinterpret_cast<float2*>(base0 + n) = make_float2(c[mf][nf][0], c[mf][nf][1]);
            *reinterpret_cast<float2*>(base1 + n) = make_float2(c[mf][nf][2], c[mf][nf][3]);
        }
    }
}

// ---------------------------------------------------------------------------
// Kernel C (R13/R14 config): per-element rescan at 3 CTAs/SM with LOGISTIC
// quantile bucketing bk = 4096*sigmoid(1.6*v) -> lambda ~= 1 uniform.
// ---------------------------------------------------------------------------
#define SORT_SMEM ((N + N + NBUCKET) * 4)   // 48KB

__global__ __launch_bounds__(512, 3) void sortdot_kernel(float* __restrict__ out)
{
    const int l = blockIdx.x >> 6;
    const int b = blockIdx.x & (B - 1);
    const int tid = threadIdx.x;
    const int lane = tid & 31;
    const int wid = tid >> 5;

    extern __shared__ char sds[];
    float* Asm  = reinterpret_cast<float*>(sds);          // N floats
    float* skey = Asm + N;                                // N floats
    int*   hist = reinterpret_cast<int*>(skey + N);       // NBUCKET ints

    __shared__ float redf[16];
    __shared__ int   reds[16];

    const float* row = g_S + (((size_t)(b * L + l)) << 12);
    float k[8];
    {
        float4 v0 = *reinterpret_cast<const float4*>(row + tid * 8);
        float4 v1 = *reinterpret_cast<const float4*>(row + tid * 8 + 4);
        k[0] = v0.x; k[1] = v0.y; k[2] = v0.z; k[3] = v0.w;
        k[4] = v1.x; k[5] = v1.y; k[6] = v1.z; k[7] = v1.w;
    }
    {
        const float4* Ag = reinterpret_cast<const float4*>(g_A + l * N);
        *reinterpret_cast<float4*>(&Asm[tid * 8])     = Ag[tid * 2];
        *reinterpret_cast<float4*>(&Asm[tid * 8 + 4]) = Ag[tid * 2 + 1];
    }
    {   // zero histogram: 2 x int4 per thread
        int4* h4 = reinterpret_cast<int4*>(hist);
        h4[tid]       = make_int4(0, 0, 0, 0);
        h4[tid + 512] = make_int4(0, 0, 0, 0);
    }
    __syncthreads();

    // --- (1) single atomic pass: logistic bucket + histogram + arrival ---
    int qq[8];
    int word[8];                      // holds bucket id now; packed word later
    #pragma unroll
    for (int i = 0; i < 8; ++i) {
        float e = __expf(-1.6f * k[i]);
        int bb2 = (int)(__fdividef(4096.0f, 1.0f + e));
        word[i] = min(max(bb2, 0), NBUCKET - 1);
        qq[i] = atomicAdd(&hist[word[i]], 1);
    }
    __syncthreads();

    // --- (2) exclusive prefix sum; packed start | (cnt<<16); int4 access ---
    {
        int4* h4 = reinterpret_cast<int4*>(hist);
        int4 ha = h4[tid * 2];
        int4 hb = h4[tid * 2 + 1];
        int s = ha.x + ha.y + ha.z + ha.w + hb.x + hb.y + hb.z + hb.w;
        int inc = s;
        #pragma unroll
        for (int o = 1; o < 32; o <<= 1) {
            int t = __shfl_up_sync(0xffffffffu, inc, o);
            if (lane >= o) inc += t;
        }
        if (lane == 31) reds[wid] = inc;    // warp totals (inclusive)
        __syncthreads();
        if (tid < 16) {                      // 16-lane exclusive scan of warp totals
            int x = reds[tid];
            int y = x;
            #pragma unroll
            for (int o = 1; o < 16; o <<= 1) {
                int t = __shfl_up_sync(0x0000ffffu, y, o);
                if (tid >= o) y += t;
            }
            reds[tid] = y - x;               // exclusive
        }
        __syncthreads();
        int base = inc - s + reds[wid];
        int4 oa, ob;
        oa.x = base | (ha.x << 16); base += ha.x;
        oa.y = base | (ha.y << 16); base += ha.y;
        oa.z = base | (ha.z << 16); base += ha.z;
        oa.w = base | (ha.w << 16); base += ha.w;
        ob.x = base | (hb.x << 16); base += hb.x;
        ob.y = base | (hb.y << 16); base += hb.y;
        ob.z = base | (hb.z << 16); base += hb.z;
        ob.w = base | (hb.w << 16);
        h4[tid * 2]     = oa;
        h4[tid * 2 + 1] = ob;
        __syncthreads();
    }

    // --- (3) scatter; replace bucket id with packed word (bk dead after) ---
    #pragma unroll
    for (int i = 0; i < 8; ++i) {
        word[i] = hist[word[i]];
        if ((word[i] >> 16) > 1) skey[(word[i] & 0xFFFF) + qq[i]] = k[i];
    }
    __syncthreads();

    // --- (4) rank + fused dot (pos recomputed; cnt==1 fast path) ---
    float acc = 0.f;
    #pragma unroll
    for (int i = 0; i < 8; ++i) {
        const float v = k[i];
        const int start = word[i] & 0xFFFF;
        const int cnt = word[i] >> 16;
        int r = start;
        if (cnt > 1) {
            const int p = start + qq[i];
            const int end = start + cnt;
            for (int q = start; q < end; ++q) {
                float u = skey[q];
                r += (u < v) || (u == v && q < p);
            }
        }
        acc += v * Asm[r];
    }

    #pragma unroll
    for (int o = 16; o; o >>= 1) acc += __shfl_down_sync(0xffffffffu, acc, o);
    if (lane == 0) redf[wid] = acc;
    __syncthreads();
    if (tid < 16) {
        float s = redf[tid];
        #pragma unroll
        for (int o = 8; o; o >>= 1) s += __shfl_xor_sync(0x0000ffffu, s, o);
        if (tid == 0) out[b * L + l] = g_C[l] - s;
    }
}

// ---------------------------------------------------------------------------
extern "C" void kernel_launch(void* const* d_in, const int* in_sizes, int n_in,
                              void* d_out, int out_size)
{
    const float* X       = (const float*)d_in[0];   // [B, N, D]
    const float* theta_v = (const float*)d_in[1];   // [L, D]
    const float* ref     = (const float*)d_in[2];   // [M, L]
    const float* weight  = (const float*)d_in[3];   // [L, M]
    float* out = (float*)d_out;                     // [B, L]

    static bool attr_set = false;
    if (!attr_set) {
        cudaFuncSetAttribute(gemm_mma_kernel,
                             cudaFuncAttributeMaxDynamicSharedMemorySize, GEMM_SMEM);
        cudaFuncSetAttribute(sortdot_kernel,
                             cudaFuncAttributeMaxDynamicSharedMemorySize, SORT_SMEM);
        attr_set = true;
    }

    noop_kernel<<<1, 32>>>();   // two noops: absolute launch index 3 -> gemm
    noop_kernel<<<1, 32>>>();
    precompute_kernel<<<L, 256>>>(theta_v, ref, weight);
    gemm_mma_kernel<<<(B * N) / 64, 128, GEMM_SMEM>>>(X);
    sortdot_kernel<<<B * L, 512, SORT_SMEM>>>(out);
}